// round 2
// baseline (speedup 1.0000x reference)
#include <cuda_runtime.h>
#include <cuda_bf16.h>
#include <math.h>

#define Bc 4
#define Hc 128
#define Wc 128
#define Cc 192
#define NHc 6
#define WSc 16
#define SSc 8
#define Nc 256
#define HDc 32
#define NPIX (Bc*Hc*Wc)            // 65536
#define ATT_SCALE 0.17677669529663687f

// ---------------- scratch (device globals; no allocation allowed) ------------
__device__ float g_xn [NPIX*Cc];      // LN1 output
__device__ float g_xw [NPIX*Cc];      // shifted+windowed LN1 output
__device__ float g_qkv[NPIX*3*Cc];    // qkv per window-token
__device__ float g_at [NPIX*Cc];      // attention output (window order)
__device__ float g_pw [NPIX*Cc];      // proj output (window order)
__device__ float g_cv1[NPIX*64];      // conv1+gelu
__device__ float g_cv2[NPIX*Cc];      // conv2
__device__ float g_y  [NPIX*Cc];      // residual sum
__device__ float g_yn [NPIX*Cc];      // LN2 output
__device__ float g_h  [NPIX*4*Cc];    // fc1+gelu
__device__ float g_pp [Bc*64*Cc];     // pooling partials
__device__ float g_ca [Bc*Cc];        // channel attention
__device__ float g_bt [NHc*Nc*Nc];    // rel-pos bias table [h][n][m]

__device__ __forceinline__ float gelu_exact(float x) {
    return 0.5f * x * (1.f + erff(x * 0.70710678118654752f));
}

// ---------------- LayerNorm over C=192 ---------------------------------------
__global__ void ln_kernel(const float* __restrict__ x, const float* __restrict__ g,
                          const float* __restrict__ b, float* __restrict__ out) {
    int t = blockIdx.x;
    int c = threadIdx.x;
    __shared__ float s1[256], s2[256];
    float v = (c < Cc) ? x[t*Cc + c] : 0.f;
    s1[c] = v; s2[c] = v*v;
    __syncthreads();
    #pragma unroll
    for (int st = 128; st > 0; st >>= 1) {
        if (c < st) { s1[c] += s1[c+st]; s2[c] += s2[c+st]; }
        __syncthreads();
    }
    float m   = s1[0] * (1.f/Cc);
    float var = s2[0] * (1.f/Cc) - m*m;
    float inv = rsqrtf(var + 1e-5f);
    if (c < Cc) out[t*Cc + c] = (v - m) * inv * g[c] + b[c];
}

// ---------------- shift + window partition gather ----------------------------
__global__ void gather_kernel(const float* __restrict__ xn, float* __restrict__ xw) {
    int idx = blockIdx.x * 256 + threadIdx.x;
    if (idx >= NPIX*Cc) return;
    int c   = idx % Cc;
    int tw  = idx / Cc;
    int n   = tw & 255, win = tw >> 8;
    int b   = win >> 6, wl = win & 63;
    int hh  = (wl >> 3) * WSc + (n >> 4);
    int ww  = (wl & 7)  * WSc + (n & 15);
    int sh  = (hh + SSc) & 127, sw = (ww + SSc) & 127;
    xw[idx] = xn[((b*Hc + sh)*Wc + sw)*Cc + c];
}

// ---------------- tiled GEMM: C[M][N] = A[M][K] @ W[K][N] + bias -------------
// TM=64 TN=64 TK=32, 256 threads, 4x4 per thread.
// mode 0: bias; mode 1: bias+GELU; mode 2: bias + R (residual add)
__global__ void gemm_kernel(const float* __restrict__ A, const float* __restrict__ W,
                            const float* __restrict__ bias, float* __restrict__ C,
                            int K, int N, int mode, const float* __restrict__ R) {
    __shared__ float As[32][65];
    __shared__ float Ws[32][64];
    int m0 = blockIdx.x * 64, n0 = blockIdx.y * 64;
    int tid = threadIdx.x;
    int tx = tid & 15, ty = tid >> 4;
    float acc[4][4] = {};
    int kk = tid & 31, rb = tid >> 5;
    int nn = tid & 63, kb = tid >> 6;
    for (int k0 = 0; k0 < K; k0 += 32) {
        #pragma unroll
        for (int i = 0; i < 8; i++) {
            int r = rb + i*8;
            As[kk][r] = A[(size_t)(m0 + r) * K + k0 + kk];
        }
        #pragma unroll
        for (int i = 0; i < 8; i++) {
            int k = kb + i*4;
            Ws[k][nn] = W[(size_t)(k0 + k) * N + n0 + nn];
        }
        __syncthreads();
        #pragma unroll
        for (int k = 0; k < 32; k++) {
            float a0 = As[k][ty*4+0], a1 = As[k][ty*4+1];
            float a2 = As[k][ty*4+2], a3 = As[k][ty*4+3];
            float4 wv = *reinterpret_cast<const float4*>(&Ws[k][tx*4]);
            acc[0][0] += a0*wv.x; acc[0][1] += a0*wv.y; acc[0][2] += a0*wv.z; acc[0][3] += a0*wv.w;
            acc[1][0] += a1*wv.x; acc[1][1] += a1*wv.y; acc[1][2] += a1*wv.z; acc[1][3] += a1*wv.w;
            acc[2][0] += a2*wv.x; acc[2][1] += a2*wv.y; acc[2][2] += a2*wv.z; acc[2][3] += a2*wv.w;
            acc[3][0] += a3*wv.x; acc[3][1] += a3*wv.y; acc[3][2] += a3*wv.z; acc[3][3] += a3*wv.w;
        }
        __syncthreads();
    }
    #pragma unroll
    for (int i = 0; i < 4; i++) {
        int r = m0 + ty*4 + i;
        #pragma unroll
        for (int j = 0; j < 4; j++) {
            int cc = n0 + tx*4 + j;
            float v = acc[i][j] + bias[cc];
            if (mode == 1)      v = gelu_exact(v);
            else if (mode == 2) v += R[(size_t)r * N + cc];
            C[(size_t)r * N + cc] = v;
        }
    }
}

// ---------------- direct 3x3 SAME conv (NHWC, HWIO weights) ------------------
// block: 64 consecutive pixels in one row x 64 output channels.
__global__ void conv3_kernel(const float* __restrict__ X, const float* __restrict__ Wt,
                             const float* __restrict__ bias, float* __restrict__ Y,
                             int Cin, int Cout, int mode) {
    __shared__ float As[32][65];
    __shared__ float Ws[32][64];
    int ptile = blockIdx.x;              // 1024 tiles of 64 pixels
    int n0 = blockIdx.y * 64;
    int b  = ptile >> 8;
    int h  = (ptile & 255) >> 1;
    int w0 = (ptile & 1) * 64;
    int tid = threadIdx.x;
    int tx = tid & 15, ty = tid >> 4;
    float acc[4][4] = {};
    int kk = tid & 31, rb = tid >> 5;
    int nn = tid & 63, kb = tid >> 6;
    int nchunks = Cin / 32;
    for (int tap = 0; tap < 9; tap++) {
        int dh = tap/3 - 1, dw = tap%3 - 1;
        int ih = h + dh;
        bool rowok = (ih >= 0 && ih < Hc);
        for (int cc = 0; cc < nchunks; cc++) {
            int ci0 = cc * 32;
            #pragma unroll
            for (int i = 0; i < 8; i++) {
                int pix = rb + i*8;
                int iw = w0 + pix + dw;
                float v = 0.f;
                if (rowok && iw >= 0 && iw < Wc)
                    v = X[(size_t)((b*Hc + ih)*Wc + iw) * Cin + ci0 + kk];
                As[kk][pix] = v;
            }
            #pragma unroll
            for (int i = 0; i < 8; i++) {
                int k = kb + i*4;
                Ws[k][nn] = Wt[(size_t)(tap*Cin + ci0 + k) * Cout + n0 + nn];
            }
            __syncthreads();
            #pragma unroll
            for (int k = 0; k < 32; k++) {
                float a0 = As[k][ty*4+0], a1 = As[k][ty*4+1];
                float a2 = As[k][ty*4+2], a3 = As[k][ty*4+3];
                float4 wv = *reinterpret_cast<const float4*>(&Ws[k][tx*4]);
                acc[0][0] += a0*wv.x; acc[0][1] += a0*wv.y; acc[0][2] += a0*wv.z; acc[0][3] += a0*wv.w;
                acc[1][0] += a1*wv.x; acc[1][1] += a1*wv.y; acc[1][2] += a1*wv.z; acc[1][3] += a1*wv.w;
                acc[2][0] += a2*wv.x; acc[2][1] += a2*wv.y; acc[2][2] += a2*wv.z; acc[2][3] += a2*wv.w;
                acc[3][0] += a3*wv.x; acc[3][1] += a3*wv.y; acc[3][2] += a3*wv.z; acc[3][3] += a3*wv.w;
            }
            __syncthreads();
        }
    }
    #pragma unroll
    for (int i = 0; i < 4; i++) {
        int p = (b*Hc + h)*Wc + w0 + ty*4 + i;
        #pragma unroll
        for (int j = 0; j < 4; j++) {
            int c = n0 + tx*4 + j;
            float v = acc[i][j] + bias[c];
            if (mode == 1) v = gelu_exact(v);
            Y[(size_t)p * Cout + c] = v;
        }
    }
}

// ---------------- global average pool partials -------------------------------
__global__ void pool_kernel(const float* __restrict__ cv2, float* __restrict__ pp) {
    int blk = blockIdx.x;        // 4*64 blocks
    int b = blk >> 6, chunk = blk & 63;
    int c = threadIdx.x;         // 192
    float s = 0.f;
    int base = b*16384 + chunk*256;
    for (int p = 0; p < 256; p++) s += cv2[(size_t)(base + p)*Cc + c];
    pp[blk*Cc + c] = s;
}

// ---------------- channel attention (single block) ---------------------------
__global__ void ca_kernel(const float* __restrict__ pp,
                          const float* __restrict__ w1, const float* __restrict__ b1,
                          const float* __restrict__ w2, const float* __restrict__ b2,
                          float* __restrict__ ca) {
    __shared__ float pooled[Bc*Cc];
    __shared__ float t1[Bc*6];
    int tid = threadIdx.x;
    for (int i = tid; i < Bc*Cc; i += 256) {
        int b = i / Cc, c = i % Cc;
        float s = 0.f;
        for (int j = 0; j < 64; j++) s += pp[(b*64 + j)*Cc + c];
        pooled[i] = s * (1.f/16384.f);
    }
    __syncthreads();
    if (tid < Bc*6) {
        int b = tid / 6, j = tid % 6;
        float s = b1[j];
        for (int c = 0; c < Cc; c++) s += pooled[b*Cc + c] * w1[c*6 + j];
        t1[tid] = fmaxf(s, 0.f);
    }
    __syncthreads();
    for (int i = tid; i < Bc*Cc; i += 256) {
        int b = i / Cc, c = i % Cc;
        float s = b2[c];
        #pragma unroll
        for (int j = 0; j < 6; j++) s += t1[b*6 + j] * w2[j*Cc + c];
        ca[i] = 1.f / (1.f + expf(-s));
    }
}

// ---------------- relative-position bias table -------------------------------
__global__ void bias_kernel(const float* __restrict__ rpb, const int* __restrict__ rpi,
                            float* __restrict__ bt) {
    int idx = blockIdx.x * 256 + threadIdx.x;
    if (idx >= NHc*Nc*Nc) return;
    int h = idx / (Nc*Nc), nm = idx % (Nc*Nc);
    bt[idx] = rpb[rpi[nm]*NHc + h];
}

// ---------------- flash-style window attention -------------------------------
// grid (256 windows, 6 heads), 256 threads = 1 query row each.
__global__ void attn_kernel(const float* __restrict__ qkv, const float* __restrict__ bt,
                            const float* __restrict__ mask, float* __restrict__ out) {
    extern __shared__ float sm[];
    float* Ks = sm;            // 256*32
    float* Vs = sm + Nc*HDc;   // 256*32
    int win = blockIdx.x, h = blockIdx.y;
    int n = threadIdx.x;
    for (int idx = n; idx < Nc*HDc; idx += 256) {
        int m = idx >> 5, d = idx & 31;
        const float* row = qkv + (size_t)(win*Nc + m)*576 + h*HDc + d;
        Ks[idx] = row[192];
        Vs[idx] = row[384];
    }
    float q[HDc];
    const float* qrow = qkv + (size_t)(win*Nc + n)*576 + h*HDc;
    #pragma unroll
    for (int d = 0; d < HDc; d++) q[d] = qrow[d] * ATT_SCALE;
    __syncthreads();
    const float* brow = bt   + (size_t)h*Nc*Nc + n*Nc;
    const float* mrow = mask + (size_t)(win & 63)*Nc*Nc + n*Nc;
    float mx = -1e30f, l = 0.f;
    float acc[HDc];
    #pragma unroll
    for (int d = 0; d < HDc; d++) acc[d] = 0.f;
    for (int m = 0; m < Nc; m++) {
        const float* kr = Ks + m*HDc;
        float s = 0.f;
        #pragma unroll
        for (int d = 0; d < HDc; d++) s += q[d]*kr[d];
        s += brow[m] + mrow[m];
        const float* vr = Vs + m*HDc;
        if (s > mx) {
            float sc = __expf(mx - s);
            l = l*sc + 1.f;
            #pragma unroll
            for (int d = 0; d < HDc; d++) acc[d] = acc[d]*sc + vr[d];
            mx = s;
        } else {
            float p = __expf(s - mx);
            l += p;
            #pragma unroll
            for (int d = 0; d < HDc; d++) acc[d] += p*vr[d];
        }
    }
    float inv = 1.f / l;
    float* orow = out + (size_t)(win*Nc + n)*Cc + h*HDc;
    #pragma unroll
    for (int d = 0; d < HDc; d++) orow[d] = acc[d]*inv;
}

// ---------------- residual combine (window-reverse + unshift inline) ---------
__global__ void combine_kernel(const float* __restrict__ x, const float* __restrict__ pw,
                               const float* __restrict__ cv2, const float* __restrict__ ca,
                               float* __restrict__ y) {
    int idx = blockIdx.x * 256 + threadIdx.x;
    if (idx >= NPIX*Cc) return;
    int c = idx % Cc;
    int p = idx / Cc;
    int b  = p >> 14;
    int oh = (p >> 7) & 127, ow = p & 127;
    int hh = (oh + Hc - SSc) & 127, ww = (ow + Wc - SSc) & 127;
    int win = b*64 + (hh >> 4)*8 + (ww >> 4);
    int n   = (hh & 15)*16 + (ww & 15);
    y[idx] = x[idx] + pw[(size_t)(win*Nc + n)*Cc + c] + cv2[idx]*ca[b*Cc + c]*0.01f;
}

// ---------------- launch -----------------------------------------------------
extern "C" void kernel_launch(void* const* d_in, const int* in_sizes, int n_in,
                              void* d_out, int out_size) {
    const float* x       = (const float*)d_in[0];
    const float* qkv_w   = (const float*)d_in[1];
    const float* qkv_b   = (const float*)d_in[2];
    const float* proj_w  = (const float*)d_in[3];
    const float* proj_b  = (const float*)d_in[4];
    const float* rpb     = (const float*)d_in[5];
    const float* n1w     = (const float*)d_in[6];
    const float* n1b     = (const float*)d_in[7];
    const float* n2w     = (const float*)d_in[8];
    const float* n2b     = (const float*)d_in[9];
    const float* c1w     = (const float*)d_in[10];
    const float* c1b     = (const float*)d_in[11];
    const float* c2w     = (const float*)d_in[12];
    const float* c2b     = (const float*)d_in[13];
    const float* ca1w    = (const float*)d_in[14];
    const float* ca1b    = (const float*)d_in[15];
    const float* ca2w    = (const float*)d_in[16];
    const float* ca2b    = (const float*)d_in[17];
    const float* fc1w    = (const float*)d_in[18];
    const float* fc1b    = (const float*)d_in[19];
    const float* fc2w    = (const float*)d_in[20];
    const float* fc2b    = (const float*)d_in[21];
    const int*   rpi     = (const int*)d_in[22];
    const float* amask   = (const float*)d_in[23];
    float* out = (float*)d_out;

    float *xn, *xw, *qkvb, *at, *pw, *cv1, *cv2, *y, *yn, *hb, *pp, *cab, *bt;
    cudaGetSymbolAddress((void**)&xn,   g_xn);
    cudaGetSymbolAddress((void**)&xw,   g_xw);
    cudaGetSymbolAddress((void**)&qkvb, g_qkv);
    cudaGetSymbolAddress((void**)&at,   g_at);
    cudaGetSymbolAddress((void**)&pw,   g_pw);
    cudaGetSymbolAddress((void**)&cv1,  g_cv1);
    cudaGetSymbolAddress((void**)&cv2,  g_cv2);
    cudaGetSymbolAddress((void**)&y,    g_y);
    cudaGetSymbolAddress((void**)&yn,   g_yn);
    cudaGetSymbolAddress((void**)&hb,   g_h);
    cudaGetSymbolAddress((void**)&pp,   g_pp);
    cudaGetSymbolAddress((void**)&cab,  g_ca);
    cudaGetSymbolAddress((void**)&bt,   g_bt);

    static bool attr_set = false;
    if (!attr_set) {
        cudaFuncSetAttribute(attn_kernel, cudaFuncAttributeMaxDynamicSharedMemorySize,
                             2*Nc*HDc*sizeof(float));
        attr_set = true;
    }

    // LN1
    ln_kernel<<<NPIX, 256>>>(x, n1w, n1b, xn);
    // conv branch
    conv3_kernel<<<dim3(1024, 1), 256>>>(xn, c1w, c1b, cv1, Cc, 64, 1);
    conv3_kernel<<<dim3(1024, 3), 256>>>(cv1, c2w, c2b, cv2, 64, Cc, 0);
    pool_kernel<<<Bc*64, Cc>>>(cv2, pp);
    ca_kernel<<<1, 256>>>(pp, ca1w, ca1b, ca2w, ca2b, cab);
    // attention branch
    gather_kernel<<<(NPIX*Cc + 255)/256, 256>>>(xn, xw);
    gemm_kernel<<<dim3(NPIX/64, 9), 256>>>(xw, qkv_w, qkv_b, qkvb, Cc, 3*Cc, 0, nullptr);
    bias_kernel<<<(NHc*Nc*Nc + 255)/256, 256>>>(rpb, rpi, bt);
    attn_kernel<<<dim3(256, NHc), 256, 2*Nc*HDc*sizeof(float)>>>(qkvb, bt, amask, at);
    gemm_kernel<<<dim3(NPIX/64, 3), 256>>>(at, proj_w, proj_b, pw, Cc, Cc, 0, nullptr);
    // residual combine
    combine_kernel<<<(NPIX*Cc + 255)/256, 256>>>(x, pw, cv2, cab, y);
    // MLP
    ln_kernel<<<NPIX, 256>>>(y, n2w, n2b, yn);
    gemm_kernel<<<dim3(NPIX/64, 12), 256>>>(yn, fc1w, fc1b, hb, Cc, 4*Cc, 1, nullptr);
    gemm_kernel<<<dim3(NPIX/64, 3), 256>>>(hb, fc2w, fc2b, out, 4*Cc, Cc, 2, y);
}

// round 3
// speedup vs baseline: 2.3056x; 2.3056x over previous
#include <cuda_runtime.h>
#include <cuda_bf16.h>
#include <math.h>
#include <stdint.h>

typedef __nv_bfloat16 bf16;

#define Bc 4
#define Hc 128
#define Wc 128
#define Cc 192
#define NHc 6
#define WSc 16
#define SSc 8
#define Nc 256
#define HDc 32
#define NPIX (Bc*Hc*Wc)            // 65536
#define ATT_SCALE 0.17677669529663687f

// ---------------- scratch (device globals; no allocation allowed) ------------
__device__ bf16  g_xnb[NPIX*Cc];            // LN1 output (bf16)
__device__ bf16  g_xwb[NPIX*Cc];            // shifted+windowed LN1 (bf16)
__device__ float g_qkv[(size_t)NPIX*3*Cc];  // qkv (fp32)
__device__ bf16  g_atb[NPIX*Cc];            // attention out (bf16, window order)
__device__ float g_pw [NPIX*Cc];            // proj out (fp32, window order)
__device__ bf16  g_cv1b[NPIX*64];           // conv1+gelu (bf16)
__device__ float g_cv2[NPIX*Cc];            // conv2 (fp32)
__device__ float g_y  [NPIX*Cc];            // residual sum
__device__ bf16  g_ynb[NPIX*Cc];            // LN2 out (bf16)
__device__ bf16  g_hb [(size_t)NPIX*4*Cc]; // fc1+gelu (bf16)
__device__ float g_pp [Bc*64*Cc];
__device__ float g_ca [Bc*Cc];
__device__ float g_btT[NHc*Nc*Nc];          // rel-pos bias TRANSPOSED [h][m][n]
// bf16 weights
__device__ bf16  g_wqkv [Cc*3*Cc];
__device__ bf16  g_wproj[Cc*Cc];
__device__ bf16  g_wfc1 [Cc*4*Cc];
__device__ bf16  g_wfc2 [4*Cc*Cc];
__device__ bf16  g_wc1  [9*Cc*64];
__device__ bf16  g_wc2  [9*64*Cc];

__device__ __forceinline__ float gelu_exact(float x) {
    return 0.5f * x * (1.f + erff(x * 0.70710678118654752f));
}

// ---------------- fp32 -> bf16 convert ---------------------------------------
__global__ void f2b_kernel(const float* __restrict__ a, bf16* __restrict__ o, int n) {
    int i = blockIdx.x * 256 + threadIdx.x;
    if (i < n) o[i] = __float2bfloat16(a[i]);
}

// ---------------- LayerNorm over C=192, bf16 out ------------------------------
__global__ void ln_kernel(const float* __restrict__ x, const float* __restrict__ g,
                          const float* __restrict__ b, bf16* __restrict__ out) {
    int t = blockIdx.x;
    int c = threadIdx.x;
    __shared__ float s1[256], s2[256];
    float v = (c < Cc) ? x[t*Cc + c] : 0.f;
    s1[c] = v; s2[c] = v*v;
    __syncthreads();
    #pragma unroll
    for (int st = 128; st > 0; st >>= 1) {
        if (c < st) { s1[c] += s1[c+st]; s2[c] += s2[c+st]; }
        __syncthreads();
    }
    float m   = s1[0] * (1.f/Cc);
    float var = s2[0] * (1.f/Cc) - m*m;
    float inv = rsqrtf(var + 1e-5f);
    if (c < Cc) out[t*Cc + c] = __float2bfloat16((v - m) * inv * g[c] + b[c]);
}

// ---------------- shift + window partition gather (bf16) ----------------------
__global__ void gather_kernel(const bf16* __restrict__ xn, bf16* __restrict__ xw) {
    int idx = blockIdx.x * 256 + threadIdx.x;
    if (idx >= NPIX*Cc) return;
    int c   = idx % Cc;
    int tw  = idx / Cc;
    int n   = tw & 255, win = tw >> 8;
    int b   = win >> 6, wl = win & 63;
    int hh  = (wl >> 3) * WSc + (n >> 4);
    int ww  = (wl & 7)  * WSc + (n & 15);
    int sh  = (hh + SSc) & 127, sw = (ww + SSc) & 127;
    xw[idx] = xn[((b*Hc + sh)*Wc + sw)*Cc + c];
}

// ---------------- bf16 tensor-core GEMM --------------------------------------
// Tile 128x64x32, 256 threads = 8 warps (4 M x 2 N), warp tile 32x32.
// MODE 0: bias -> fp32 out; MODE 1: bias+GELU -> bf16 out; MODE 2: bias+res -> fp32.
#define AP 40
#define BP 40

__device__ __forceinline__ void mma_bf16(float* c, const uint32_t* a, const uint32_t* b) {
    asm volatile(
        "mma.sync.aligned.m16n8k16.row.col.f32.bf16.bf16.f32 "
        "{%0,%1,%2,%3}, {%4,%5,%6,%7}, {%8,%9}, {%0,%1,%2,%3};\n"
        : "+f"(c[0]), "+f"(c[1]), "+f"(c[2]), "+f"(c[3])
        : "r"(a[0]), "r"(a[1]), "r"(a[2]), "r"(a[3]), "r"(b[0]), "r"(b[1]));
}

template<int MODE>
__global__ __launch_bounds__(256) void mma_gemm(
        const bf16* __restrict__ A, const bf16* __restrict__ W,
        const float* __restrict__ bias, void* __restrict__ Cout_,
        const float* __restrict__ Rres, int K, int N) {
    __shared__ __align__(16) bf16 As[128*AP];
    __shared__ __align__(16) bf16 Bs[64*BP];
    int tid = threadIdx.x;
    int m0 = blockIdx.x * 128, n0 = blockIdx.y * 64;
    int warp = tid >> 5, lane = tid & 31;
    int wm = warp & 3, wn = warp >> 2;
    int g = lane >> 2, tg = lane & 3;
    float acc[2][4][4];
    #pragma unroll
    for (int a = 0; a < 2; a++)
        #pragma unroll
        for (int b = 0; b < 4; b++)
            #pragma unroll
            for (int c = 0; c < 4; c++) acc[a][b][c] = 0.f;

    for (int k0 = 0; k0 < K; k0 += 32) {
        #pragma unroll
        for (int i = 0; i < 4; i++) {
            int idx = tid + i*256;
            int r = idx >> 3, kq = idx & 7;
            *(uint2*)&As[r*AP + kq*4] =
                *(const uint2*)(A + (size_t)(m0+r)*K + k0 + kq*4);
        }
        #pragma unroll
        for (int i = 0; i < 2; i++) {
            int idx = tid + i*256;
            int k = idx >> 4, ng = idx & 15;
            bf16 tmp[4];
            *(uint2*)tmp = *(const uint2*)(W + (size_t)(k0+k)*N + n0 + ng*4);
            #pragma unroll
            for (int j = 0; j < 4; j++) Bs[(ng*4+j)*BP + k] = tmp[j];
        }
        __syncthreads();
        #pragma unroll
        for (int kk = 0; kk < 32; kk += 16) {
            uint32_t af[2][4], bf[4][2];
            #pragma unroll
            for (int mi = 0; mi < 2; mi++) {
                int rb = wm*32 + mi*16 + g;
                af[mi][0] = *(const uint32_t*)&As[(rb  )*AP + kk + tg*2];
                af[mi][1] = *(const uint32_t*)&As[(rb+8)*AP + kk + tg*2];
                af[mi][2] = *(const uint32_t*)&As[(rb  )*AP + kk + 8 + tg*2];
                af[mi][3] = *(const uint32_t*)&As[(rb+8)*AP + kk + 8 + tg*2];
            }
            #pragma unroll
            for (int ni = 0; ni < 4; ni++) {
                int cb = wn*32 + ni*8 + g;
                bf[ni][0] = *(const uint32_t*)&Bs[cb*BP + kk + tg*2];
                bf[ni][1] = *(const uint32_t*)&Bs[cb*BP + kk + 8 + tg*2];
            }
            #pragma unroll
            for (int mi = 0; mi < 2; mi++)
                #pragma unroll
                for (int ni = 0; ni < 4; ni++)
                    mma_bf16(acc[mi][ni], af[mi], bf[ni]);
        }
        __syncthreads();
    }
    // epilogue
    #pragma unroll
    for (int mi = 0; mi < 2; mi++) {
        #pragma unroll
        for (int ni = 0; ni < 4; ni++) {
            int r1 = m0 + wm*32 + mi*16 + g;
            int r2 = r1 + 8;
            int cg = n0 + wn*32 + ni*8 + tg*2;
            float b0 = bias[cg], b1 = bias[cg+1];
            float v00 = acc[mi][ni][0] + b0, v01 = acc[mi][ni][1] + b1;
            float v10 = acc[mi][ni][2] + b0, v11 = acc[mi][ni][3] + b1;
            if (MODE == 0) {
                float* C = (float*)Cout_;
                *(float2*)(C + (size_t)r1*N + cg) = make_float2(v00, v01);
                *(float2*)(C + (size_t)r2*N + cg) = make_float2(v10, v11);
            } else if (MODE == 1) {
                bf16* C = (bf16*)Cout_;
                *(__nv_bfloat162*)(C + (size_t)r1*N + cg) =
                    __floats2bfloat162_rn(gelu_exact(v00), gelu_exact(v01));
                *(__nv_bfloat162*)(C + (size_t)r2*N + cg) =
                    __floats2bfloat162_rn(gelu_exact(v10), gelu_exact(v11));
            } else {
                float* C = (float*)Cout_;
                float2 ra = *(const float2*)(Rres + (size_t)r1*N + cg);
                float2 rb2 = *(const float2*)(Rres + (size_t)r2*N + cg);
                *(float2*)(C + (size_t)r1*N + cg) = make_float2(v00+ra.x, v01+ra.y);
                *(float2*)(C + (size_t)r2*N + cg) = make_float2(v10+rb2.x, v11+rb2.y);
            }
        }
    }
}

// ---------------- bf16 tensor-core 3x3 conv (implicit GEMM) -------------------
// Block: one full image row (128 pixels) x 64 output channels.
template<int MODE>
__global__ __launch_bounds__(256) void mma_conv(
        const bf16* __restrict__ X, const bf16* __restrict__ Wt,
        const float* __restrict__ bias, void* __restrict__ Yout,
        int Cin, int Cout) {
    __shared__ __align__(16) bf16 As[128*AP];
    __shared__ __align__(16) bf16 Bs[64*BP];
    int bi = blockIdx.x;
    int b = bi >> 7, h = bi & 127;
    int n0 = blockIdx.y * 64;
    int tid = threadIdx.x;
    int warp = tid >> 5, lane = tid & 31;
    int wm = warp & 3, wn = warp >> 2;
    int g = lane >> 2, tg = lane & 3;
    float acc[2][4][4];
    #pragma unroll
    for (int a = 0; a < 2; a++)
        #pragma unroll
        for (int c = 0; c < 4; c++)
            #pragma unroll
            for (int d = 0; d < 4; d++) acc[a][c][d] = 0.f;

    for (int tap = 0; tap < 9; tap++) {
        int dh = tap/3 - 1, dw = tap%3 - 1;
        int ih = h + dh;
        bool rowok = (ih >= 0 && ih < Hc);
        const bf16* Xbase = X + (size_t)((b*Hc + ih)*Wc) * Cin;
        for (int ci0 = 0; ci0 < Cin; ci0 += 32) {
            #pragma unroll
            for (int i = 0; i < 4; i++) {
                int idx = tid + i*256;
                int r = idx >> 3, kq = idx & 7;
                int iw = r + dw;
                uint2 v = make_uint2(0u, 0u);
                if (rowok && iw >= 0 && iw < Wc)
                    v = *(const uint2*)(Xbase + (size_t)iw*Cin + ci0 + kq*4);
                *(uint2*)&As[r*AP + kq*4] = v;
            }
            #pragma unroll
            for (int i = 0; i < 2; i++) {
                int idx = tid + i*256;
                int k = idx >> 4, ng = idx & 15;
                bf16 tmp[4];
                *(uint2*)tmp = *(const uint2*)(Wt + (size_t)(tap*Cin + ci0 + k)*Cout + n0 + ng*4);
                #pragma unroll
                for (int j = 0; j < 4; j++) Bs[(ng*4+j)*BP + k] = tmp[j];
            }
            __syncthreads();
            #pragma unroll
            for (int kk = 0; kk < 32; kk += 16) {
                uint32_t af[2][4], bfr[4][2];
                #pragma unroll
                for (int mi = 0; mi < 2; mi++) {
                    int rb = wm*32 + mi*16 + g;
                    af[mi][0] = *(const uint32_t*)&As[(rb  )*AP + kk + tg*2];
                    af[mi][1] = *(const uint32_t*)&As[(rb+8)*AP + kk + tg*2];
                    af[mi][2] = *(const uint32_t*)&As[(rb  )*AP + kk + 8 + tg*2];
                    af[mi][3] = *(const uint32_t*)&As[(rb+8)*AP + kk + 8 + tg*2];
                }
                #pragma unroll
                for (int ni = 0; ni < 4; ni++) {
                    int cb = wn*32 + ni*8 + g;
                    bfr[ni][0] = *(const uint32_t*)&Bs[cb*BP + kk + tg*2];
                    bfr[ni][1] = *(const uint32_t*)&Bs[cb*BP + kk + 8 + tg*2];
                }
                #pragma unroll
                for (int mi = 0; mi < 2; mi++)
                    #pragma unroll
                    for (int ni = 0; ni < 4; ni++)
                        mma_bf16(acc[mi][ni], af[mi], bfr[ni]);
            }
            __syncthreads();
        }
    }
    #pragma unroll
    for (int mi = 0; mi < 2; mi++) {
        #pragma unroll
        for (int ni = 0; ni < 4; ni++) {
            int p1 = (b*Hc + h)*Wc + wm*32 + mi*16 + g;
            int p2 = p1 + 8;
            int cg = n0 + wn*32 + ni*8 + tg*2;
            float b0 = bias[cg], b1 = bias[cg+1];
            float v00 = acc[mi][ni][0] + b0, v01 = acc[mi][ni][1] + b1;
            float v10 = acc[mi][ni][2] + b0, v11 = acc[mi][ni][3] + b1;
            if (MODE == 1) {
                bf16* Y = (bf16*)Yout;
                *(__nv_bfloat162*)(Y + (size_t)p1*Cout + cg) =
                    __floats2bfloat162_rn(gelu_exact(v00), gelu_exact(v01));
                *(__nv_bfloat162*)(Y + (size_t)p2*Cout + cg) =
                    __floats2bfloat162_rn(gelu_exact(v10), gelu_exact(v11));
            } else {
                float* Y = (float*)Yout;
                *(float2*)(Y + (size_t)p1*Cout + cg) = make_float2(v00, v01);
                *(float2*)(Y + (size_t)p2*Cout + cg) = make_float2(v10, v11);
            }
        }
    }
}

// ---------------- global average pool partials -------------------------------
__global__ void pool_kernel(const float* __restrict__ cv2, float* __restrict__ pp) {
    int blk = blockIdx.x;
    int b = blk >> 6, chunk = blk & 63;
    int c = threadIdx.x;
    float s = 0.f;
    int base = b*16384 + chunk*256;
    for (int p = 0; p < 256; p++) s += cv2[(size_t)(base + p)*Cc + c];
    pp[blk*Cc + c] = s;
}

// ---------------- channel attention ------------------------------------------
__global__ void ca_kernel(const float* __restrict__ pp,
                          const float* __restrict__ w1, const float* __restrict__ b1,
                          const float* __restrict__ w2, const float* __restrict__ b2,
                          float* __restrict__ ca) {
    __shared__ float pooled[Bc*Cc];
    __shared__ float t1[Bc*6];
    int tid = threadIdx.x;
    for (int i = tid; i < Bc*Cc; i += 256) {
        int b = i / Cc, c = i % Cc;
        float s = 0.f;
        for (int j = 0; j < 64; j++) s += pp[(b*64 + j)*Cc + c];
        pooled[i] = s * (1.f/16384.f);
    }
    __syncthreads();
    if (tid < Bc*6) {
        int b = tid / 6, j = tid % 6;
        float s = b1[j];
        for (int c = 0; c < Cc; c++) s += pooled[b*Cc + c] * w1[c*6 + j];
        t1[tid] = fmaxf(s, 0.f);
    }
    __syncthreads();
    for (int i = tid; i < Bc*Cc; i += 256) {
        int b = i / Cc, c = i % Cc;
        float s = b2[c];
        #pragma unroll
        for (int j = 0; j < 6; j++) s += t1[b*6 + j] * w2[j*Cc + c];
        ca[i] = 1.f / (1.f + expf(-s));
    }
}

// ---------------- transposed relative-position bias table [h][m][n] ----------
__global__ void biasT_kernel(const float* __restrict__ rpb, const int* __restrict__ rpi,
                             float* __restrict__ btT) {
    int idx = blockIdx.x * 256 + threadIdx.x;
    if (idx >= NHc*Nc*Nc) return;
    int h = idx / (Nc*Nc);
    int mn = idx % (Nc*Nc);
    int m = mn >> 8, n = mn & 255;
    btT[idx] = rpb[rpi[n*Nc + m]*NHc + h];   // bias[n][m] stored at [h][m][n]
}

// ---------------- flash window attention (bf16 K/V smem, coalesced tables) ---
__global__ __launch_bounds__(256) void attn_kernel(
        const float* __restrict__ qkv, const float* __restrict__ btT,
        const float* __restrict__ mask, bf16* __restrict__ out) {
    __shared__ __align__(16) bf16 Ks[Nc*HDc];
    __shared__ __align__(16) bf16 Vs[Nc*HDc];
    int win = blockIdx.x, h = blockIdx.y;
    int n = threadIdx.x;
    for (int idx = n; idx < Nc*HDc; idx += 256) {
        int m = idx >> 5, d = idx & 31;
        const float* row = qkv + (size_t)(win*Nc + m)*576 + h*HDc + d;
        Ks[idx] = __float2bfloat16(row[192]);
        Vs[idx] = __float2bfloat16(row[384]);
    }
    float q[HDc];
    const float4* q4 = (const float4*)(qkv + (size_t)(win*Nc + n)*576 + h*HDc);
    #pragma unroll
    for (int i = 0; i < 8; i++) {
        float4 v = q4[i];
        q[4*i+0] = v.x * ATT_SCALE; q[4*i+1] = v.y * ATT_SCALE;
        q[4*i+2] = v.z * ATT_SCALE; q[4*i+3] = v.w * ATT_SCALE;
    }
    __syncthreads();
    const float* brow = btT  + (size_t)h*Nc*Nc + n;          // [h][m][n], step m -> +256
    const float* mrow = mask + (size_t)(win & 63)*Nc*Nc + n; // symmetric, step m -> +256
    float mx = -1e30f, l = 0.f;
    float acc[HDc];
    #pragma unroll
    for (int d = 0; d < HDc; d++) acc[d] = 0.f;

    for (int m = 0; m < Nc; m++) {
        const uint4* kr = (const uint4*)(Ks + m*HDc);
        float s = 0.f;
        #pragma unroll
        for (int i = 0; i < 4; i++) {
            uint4 u = kr[i];
            float2 f0 = __bfloat1622float2(*(const __nv_bfloat162*)&u.x);
            float2 f1 = __bfloat1622float2(*(const __nv_bfloat162*)&u.y);
            float2 f2 = __bfloat1622float2(*(const __nv_bfloat162*)&u.z);
            float2 f3 = __bfloat1622float2(*(const __nv_bfloat162*)&u.w);
            s += q[8*i+0]*f0.x + q[8*i+1]*f0.y + q[8*i+2]*f1.x + q[8*i+3]*f1.y
               + q[8*i+4]*f2.x + q[8*i+5]*f2.y + q[8*i+6]*f3.x + q[8*i+7]*f3.y;
        }
        s += brow[m*Nc] + mrow[m*Nc];
        float newmx = fmaxf(mx, s);
        float sc = __expf(mx - newmx);
        float p  = __expf(s - newmx);
        l = l*sc + p;
        mx = newmx;
        const uint4* vr = (const uint4*)(Vs + m*HDc);
        #pragma unroll
        for (int i = 0; i < 4; i++) {
            uint4 u = vr[i];
            float2 f0 = __bfloat1622float2(*(const __nv_bfloat162*)&u.x);
            float2 f1 = __bfloat1622float2(*(const __nv_bfloat162*)&u.y);
            float2 f2 = __bfloat1622float2(*(const __nv_bfloat162*)&u.z);
            float2 f3 = __bfloat1622float2(*(const __nv_bfloat162*)&u.w);
            acc[8*i+0] = acc[8*i+0]*sc + p*f0.x;
            acc[8*i+1] = acc[8*i+1]*sc + p*f0.y;
            acc[8*i+2] = acc[8*i+2]*sc + p*f1.x;
            acc[8*i+3] = acc[8*i+3]*sc + p*f1.y;
            acc[8*i+4] = acc[8*i+4]*sc + p*f2.x;
            acc[8*i+5] = acc[8*i+5]*sc + p*f2.y;
            acc[8*i+6] = acc[8*i+6]*sc + p*f3.x;
            acc[8*i+7] = acc[8*i+7]*sc + p*f3.y;
        }
    }
    float inv = 1.f / l;
    __nv_bfloat162* orow = (__nv_bfloat162*)(out + (size_t)(win*Nc + n)*Cc + h*HDc);
    #pragma unroll
    for (int i = 0; i < 16; i++)
        orow[i] = __floats2bfloat162_rn(acc[2*i]*inv, acc[2*i+1]*inv);
}

// ---------------- residual combine -------------------------------------------
__global__ void combine_kernel(const float* __restrict__ x, const float* __restrict__ pw,
                               const float* __restrict__ cv2, const float* __restrict__ ca,
                               float* __restrict__ y) {
    int idx = blockIdx.x * 256 + threadIdx.x;
    if (idx >= NPIX*Cc) return;
    int c = idx % Cc;
    int p = idx / Cc;
    int b  = p >> 14;
    int oh = (p >> 7) & 127, ow = p & 127;
    int hh = (oh + Hc - SSc) & 127, ww = (ow + Wc - SSc) & 127;
    int win = b*64 + (hh >> 4)*8 + (ww >> 4);
    int n   = (hh & 15)*16 + (ww & 15);
    y[idx] = x[idx] + pw[(size_t)(win*Nc + n)*Cc + c] + cv2[idx]*ca[b*Cc + c]*0.01f;
}

// ---------------- launch -----------------------------------------------------
extern "C" void kernel_launch(void* const* d_in, const int* in_sizes, int n_in,
                              void* d_out, int out_size) {
    const float* x     = (const float*)d_in[0];
    const float* qkv_w = (const float*)d_in[1];
    const float* qkv_b = (const float*)d_in[2];
    const float* proj_w= (const float*)d_in[3];
    const float* proj_b= (const float*)d_in[4];
    const float* rpb   = (const float*)d_in[5];
    const float* n1w   = (const float*)d_in[6];
    const float* n1b   = (const float*)d_in[7];
    const float* n2w   = (const float*)d_in[8];
    const float* n2b   = (const float*)d_in[9];
    const float* c1w   = (const float*)d_in[10];
    const float* c1b   = (const float*)d_in[11];
    const float* c2w   = (const float*)d_in[12];
    const float* c2b   = (const float*)d_in[13];
    const float* ca1w  = (const float*)d_in[14];
    const float* ca1b  = (const float*)d_in[15];
    const float* ca2w  = (const float*)d_in[16];
    const float* ca2b  = (const float*)d_in[17];
    const float* fc1w  = (const float*)d_in[18];
    const float* fc1b  = (const float*)d_in[19];
    const float* fc2w  = (const float*)d_in[20];
    const float* fc2b  = (const float*)d_in[21];
    const int*   rpi   = (const int*)d_in[22];
    const float* amask = (const float*)d_in[23];
    float* out = (float*)d_out;

    bf16 *xnb, *xwb, *atb, *cv1b, *ynb, *hb;
    bf16 *wqkv, *wproj, *wfc1, *wfc2, *wc1, *wc2;
    float *qkvb, *pw, *cv2, *y, *pp, *cab, *btT;
    cudaGetSymbolAddress((void**)&xnb,  g_xnb);
    cudaGetSymbolAddress((void**)&xwb,  g_xwb);
    cudaGetSymbolAddress((void**)&qkvb, g_qkv);
    cudaGetSymbolAddress((void**)&atb,  g_atb);
    cudaGetSymbolAddress((void**)&pw,   g_pw);
    cudaGetSymbolAddress((void**)&cv1b, g_cv1b);
    cudaGetSymbolAddress((void**)&cv2,  g_cv2);
    cudaGetSymbolAddress((void**)&y,    g_y);
    cudaGetSymbolAddress((void**)&ynb,  g_ynb);
    cudaGetSymbolAddress((void**)&hb,   g_hb);
    cudaGetSymbolAddress((void**)&pp,   g_pp);
    cudaGetSymbolAddress((void**)&cab,  g_ca);
    cudaGetSymbolAddress((void**)&btT,  g_btT);
    cudaGetSymbolAddress((void**)&wqkv, g_wqkv);
    cudaGetSymbolAddress((void**)&wproj,g_wproj);
    cudaGetSymbolAddress((void**)&wfc1, g_wfc1);
    cudaGetSymbolAddress((void**)&wfc2, g_wfc2);
    cudaGetSymbolAddress((void**)&wc1,  g_wc1);
    cudaGetSymbolAddress((void**)&wc2,  g_wc2);

    // weight conversions (tiny)
    f2b_kernel<<<(Cc*3*Cc + 255)/256, 256>>>(qkv_w, wqkv, Cc*3*Cc);
    f2b_kernel<<<(Cc*Cc + 255)/256, 256>>>(proj_w, wproj, Cc*Cc);
    f2b_kernel<<<(Cc*4*Cc + 255)/256, 256>>>(fc1w, wfc1, Cc*4*Cc);
    f2b_kernel<<<(4*Cc*Cc + 255)/256, 256>>>(fc2w, wfc2, 4*Cc*Cc);
    f2b_kernel<<<(9*Cc*64 + 255)/256, 256>>>(c1w, wc1, 9*Cc*64);
    f2b_kernel<<<(9*64*Cc + 255)/256, 256>>>(c2w, wc2, 9*64*Cc);
    biasT_kernel<<<(NHc*Nc*Nc + 255)/256, 256>>>(rpb, rpi, btT);

    // LN1
    ln_kernel<<<NPIX, 256>>>(x, n1w, n1b, xnb);
    // conv branch
    mma_conv<1><<<dim3(Bc*Hc, 1), 256>>>(xnb, wc1, c1b, cv1b, Cc, 64);
    mma_conv<0><<<dim3(Bc*Hc, 3), 256>>>(cv1b, wc2, c2b, cv2, 64, Cc);
    pool_kernel<<<Bc*64, Cc>>>(cv2, pp);
    ca_kernel<<<1, 256>>>(pp, ca1w, ca1b, ca2w, ca2b, cab);
    // attention branch
    gather_kernel<<<(NPIX*Cc + 255)/256, 256>>>(xnb, xwb);
    mma_gemm<0><<<dim3(NPIX/128, 9), 256>>>(xwb, wqkv, qkv_b, qkvb, nullptr, Cc, 3*Cc);
    attn_kernel<<<dim3(256, NHc), 256>>>(qkvb, btT, amask, atb);
    mma_gemm<0><<<dim3(NPIX/128, 3), 256>>>(atb, wproj, proj_b, pw, nullptr, Cc, Cc);
    // residual combine
    combine_kernel<<<(NPIX*Cc + 255)/256, 256>>>(x, pw, cv2, cab, y);
    // MLP
    ln_kernel<<<NPIX, 256>>>(y, n2w, n2b, ynb);
    mma_gemm<1><<<dim3(NPIX/128, 12), 256>>>(ynb, wfc1, fc1b, hb, nullptr, Cc, 4*Cc);
    mma_gemm<2><<<dim3(NPIX/128, 3), 256>>>(hb, wfc2, fc2b, out, y, 4*Cc, Cc);
}

// round 4
// speedup vs baseline: 4.3444x; 1.8843x over previous
#include <cuda_runtime.h>
#include <cuda_bf16.h>
#include <math.h>
#include <stdint.h>

typedef __nv_bfloat16 bf16;

#define Bc 4
#define Hc 128
#define Wc 128
#define Cc 192
#define NHc 6
#define WSc 16
#define SSc 8
#define Nc 256
#define HDc 32
#define NPIX (Bc*Hc*Wc)            // 65536
#define ATT_SCALE 0.17677669529663687f

#define AP 40       // A smem row stride (bf16 elems): 80B, 16B-aligned, LDSM-friendly
#define BP2 72      // B smem row stride: 144B, 16B-aligned, conflict-free for LDSM

// ---------------- scratch (device globals) -----------------------------------
__device__ bf16  g_xnb [NPIX*Cc];
__device__ bf16  g_qkvb[(size_t)NPIX*3*Cc];
__device__ bf16  g_atb [NPIX*Cc];
__device__ bf16  g_cv1b[NPIX*64];
__device__ bf16  g_cv2b[NPIX*Cc];
__device__ float g_y   [NPIX*Cc];
__device__ bf16  g_ynb [NPIX*Cc];
__device__ bf16  g_hb  [(size_t)NPIX*4*Cc];
__device__ float g_pp  [Bc*64*Cc];
__device__ float g_ca  [Bc*Cc];
__device__ float g_btT [NHc*Nc*Nc];
__device__ bf16  g_wqkv [Cc*3*Cc];
__device__ bf16  g_wproj[Cc*Cc];
__device__ bf16  g_wfc1 [Cc*4*Cc];
__device__ bf16  g_wfc2 [4*Cc*Cc];
__device__ bf16  g_wc1  [9*Cc*64];
__device__ bf16  g_wc2  [9*64*Cc];

__device__ __forceinline__ float gelu_exact(float x) {
    return 0.5f * x * (1.f + erff(x * 0.70710678118654752f));
}

// ---------------- ptx helpers ------------------------------------------------
#define CP16(dst, src) asm volatile("cp.async.cg.shared.global [%0], [%1], 16;\n" :: "r"(dst), "l"(src))
#define CP16Z(dst, src, sz) asm volatile("cp.async.cg.shared.global [%0], [%1], 16, %2;\n" :: "r"(dst), "l"(src), "r"(sz))
#define CP_COMMIT asm volatile("cp.async.commit_group;\n")
#define CP_WAIT1  asm volatile("cp.async.wait_group 1;\n")

__device__ __forceinline__ void ldsm4(uint32_t* r, uint32_t a) {
    asm volatile("ldmatrix.sync.aligned.m8n8.x4.shared.b16 {%0,%1,%2,%3},[%4];"
        : "=r"(r[0]), "=r"(r[1]), "=r"(r[2]), "=r"(r[3]) : "r"(a));
}
__device__ __forceinline__ void ldsm4t(uint32_t* r, uint32_t a) {
    asm volatile("ldmatrix.sync.aligned.m8n8.x4.trans.shared.b16 {%0,%1,%2,%3},[%4];"
        : "=r"(r[0]), "=r"(r[1]), "=r"(r[2]), "=r"(r[3]) : "r"(a));
}
__device__ __forceinline__ void mma_bf16(float* c, const uint32_t* a, const uint32_t* b) {
    asm volatile(
        "mma.sync.aligned.m16n8k16.row.col.f32.bf16.bf16.f32 "
        "{%0,%1,%2,%3}, {%4,%5,%6,%7}, {%8,%9}, {%0,%1,%2,%3};\n"
        : "+f"(c[0]), "+f"(c[1]), "+f"(c[2]), "+f"(c[3])
        : "r"(a[0]), "r"(a[1]), "r"(a[2]), "r"(a[3]), "r"(b[0]), "r"(b[1]));
}
typedef unsigned long long u64t;
__device__ __forceinline__ u64t pk2(float lo, float hi) {
    u64t r; asm("mov.b64 %0,{%1,%2};" : "=l"(r) : "f"(lo), "f"(hi)); return r;
}
__device__ __forceinline__ float2 upk2(u64t v) {
    float2 f; asm("mov.b64 {%0,%1},%2;" : "=f"(f.x), "=f"(f.y) : "l"(v)); return f;
}
__device__ __forceinline__ u64t fma2(u64t a, u64t b, u64t c) {
    u64t d; asm("fma.rn.f32x2 %0,%1,%2,%3;" : "=l"(d) : "l"(a), "l"(b), "l"(c)); return d;
}
__device__ __forceinline__ u64t mul2(u64t a, u64t b) {
    u64t d; asm("mul.rn.f32x2 %0,%1,%2;" : "=l"(d) : "l"(a), "l"(b)); return d;
}

// ---------------- small converts ---------------------------------------------
__global__ void f2b_kernel(const float* __restrict__ a, bf16* __restrict__ o, int n) {
    int i = blockIdx.x * 256 + threadIdx.x;
    if (i < n) o[i] = __float2bfloat16(a[i]);
}
__global__ void biasT_kernel(const float* __restrict__ rpb, const int* __restrict__ rpi,
                             float* __restrict__ btT) {
    int idx = blockIdx.x * 256 + threadIdx.x;
    if (idx >= NHc*Nc*Nc) return;
    int h = idx / (Nc*Nc);
    int mn = idx % (Nc*Nc);
    int m = mn >> 8, n = mn & 255;
    btT[idx] = rpb[rpi[n*Nc + m]*NHc + h];
}

// ---------------- LayerNorm: warp per token ----------------------------------
__global__ __launch_bounds__(256) void ln_kernel(
        const float* __restrict__ x, const float* __restrict__ g,
        const float* __restrict__ b, bf16* __restrict__ out) {
    int t = (blockIdx.x * 256 + threadIdx.x) >> 5;
    int lane = threadIdx.x & 31;
    const float* row = x + (size_t)t * Cc;
    float v[6], s = 0.f, ss = 0.f;
    #pragma unroll
    for (int i = 0; i < 6; i++) {
        v[i] = row[i*32 + lane];
        s += v[i]; ss += v[i]*v[i];
    }
    #pragma unroll
    for (int o = 16; o; o >>= 1) {
        s  += __shfl_xor_sync(0xffffffffu, s, o);
        ss += __shfl_xor_sync(0xffffffffu, ss, o);
    }
    float m = s * (1.f/Cc);
    float inv = rsqrtf(ss * (1.f/Cc) - m*m + 1e-5f);
    #pragma unroll
    for (int i = 0; i < 6; i++) {
        int c = i*32 + lane;
        out[(size_t)t*Cc + c] = __float2bfloat16((v[i] - m)*inv*g[c] + b[c]);
    }
}

// ---------------- MMA compute for one 128x64x32 chunk ------------------------
__device__ __forceinline__ void mma_chunk(const bf16* As, const bf16* Bs,
        int wm, int wn, int lane, float acc[2][4][4]) {
    #pragma unroll
    for (int kk = 0; kk < 32; kk += 16) {
        uint32_t af[2][4], bq[2][4];
        #pragma unroll
        for (int mi = 0; mi < 2; mi++) {
            int r = wm*32 + mi*16 + (lane & 15);
            int kofs = kk + ((lane >> 4) << 3);
            ldsm4(af[mi], (uint32_t)__cvta_generic_to_shared(As + r*AP + kofs));
        }
        #pragma unroll
        for (int nh = 0; nh < 2; nh++) {
            int krow = kk + (lane & 7) + (lane & 8);
            int ncol = wn*32 + nh*16 + ((lane >> 4) << 3);
            ldsm4t(bq[nh], (uint32_t)__cvta_generic_to_shared(Bs + krow*BP2 + ncol));
        }
        #pragma unroll
        for (int mi = 0; mi < 2; mi++) {
            mma_bf16(acc[mi][0], af[mi], &bq[0][0]);
            mma_bf16(acc[mi][1], af[mi], &bq[0][2]);
            mma_bf16(acc[mi][2], af[mi], &bq[1][0]);
            mma_bf16(acc[mi][3], af[mi], &bq[1][2]);
        }
    }
}

// ---------------- GEMM: MODE 0 bf16; 1 gelu bf16; 2 fp32+res; 3 proj-combine -
template<int MODE, int GATHER>
__global__ __launch_bounds__(256, 2) void mma_gemm(
        const bf16* __restrict__ A, const bf16* __restrict__ W,
        const float* __restrict__ bias, void* __restrict__ Cout_,
        const float* __restrict__ Rres, const float* __restrict__ xres,
        const bf16* __restrict__ cv2b, const float* __restrict__ cab,
        int K, int N) {
    __shared__ __align__(16) bf16 As[2][128*AP];
    __shared__ __align__(16) bf16 Bs[2][32*BP2];
    int tid = threadIdx.x;
    int m0 = blockIdx.x * 128, n0 = blockIdx.y * 64;
    int warp = tid >> 5, lane = tid & 31;
    int wm = warp & 3, wn = warp >> 2;
    int g = lane >> 2, tg = lane & 3;
    int nk = K >> 5;

    auto loadA = [&](bf16* dst, int k0) {
        #pragma unroll
        for (int i = 0; i < 2; i++) {
            int idx = tid + i*256;
            int r = idx >> 2, kc = idx & 3;
            const bf16* src;
            if (GATHER) {
                int t = m0 + r; int n = t & 255, win = t >> 8;
                int b = win >> 6, wl = win & 63;
                int hh = (((wl >> 3) << 4) + (n >> 4) + SSc) & 127;
                int ww = (((wl & 7) << 4) + (n & 15) + SSc) & 127;
                src = A + ((size_t)((b*Hc + hh)*Wc + ww))*K + k0 + kc*8;
            } else {
                src = A + (size_t)(m0 + r)*K + k0 + kc*8;
            }
            CP16((uint32_t)__cvta_generic_to_shared(dst + r*AP + kc*8), src);
        }
    };
    auto loadB = [&](bf16* dst, int k0) {
        int k = tid >> 3, nc = tid & 7;
        CP16((uint32_t)__cvta_generic_to_shared(dst + k*BP2 + nc*8),
             W + (size_t)(k0 + k)*N + n0 + nc*8);
    };

    float acc[2][4][4];
    #pragma unroll
    for (int a = 0; a < 2; a++)
        #pragma unroll
        for (int b = 0; b < 4; b++)
            #pragma unroll
            for (int c = 0; c < 4; c++) acc[a][b][c] = 0.f;

    loadA(As[0], 0); loadB(Bs[0], 0);
    CP_COMMIT;
    for (int c = 0; c < nk; c++) {
        int nx = c + 1;
        if (nx < nk) { loadA(As[nx & 1], nx*32); loadB(Bs[nx & 1], nx*32); }
        CP_COMMIT;
        CP_WAIT1;
        __syncthreads();
        mma_chunk(As[c & 1], Bs[c & 1], wm, wn, lane, acc);
        __syncthreads();
    }

    #pragma unroll
    for (int mi = 0; mi < 2; mi++) {
        #pragma unroll
        for (int nj = 0; nj < 4; nj++) {
            int r1 = m0 + wm*32 + mi*16 + g;
            int r2 = r1 + 8;
            int cg = n0 + wn*32 + nj*8 + tg*2;
            float b0 = bias[cg], b1 = bias[cg+1];
            float v00 = acc[mi][nj][0] + b0, v01 = acc[mi][nj][1] + b1;
            float v10 = acc[mi][nj][2] + b0, v11 = acc[mi][nj][3] + b1;
            if (MODE == 0) {
                bf16* C = (bf16*)Cout_;
                *(__nv_bfloat162*)(C + (size_t)r1*N + cg) = __floats2bfloat162_rn(v00, v01);
                *(__nv_bfloat162*)(C + (size_t)r2*N + cg) = __floats2bfloat162_rn(v10, v11);
            } else if (MODE == 1) {
                bf16* C = (bf16*)Cout_;
                *(__nv_bfloat162*)(C + (size_t)r1*N + cg) =
                    __floats2bfloat162_rn(gelu_exact(v00), gelu_exact(v01));
                *(__nv_bfloat162*)(C + (size_t)r2*N + cg) =
                    __floats2bfloat162_rn(gelu_exact(v10), gelu_exact(v11));
            } else if (MODE == 2) {
                float* C = (float*)Cout_;
                float2 ra = *(const float2*)(Rres + (size_t)r1*N + cg);
                float2 rb = *(const float2*)(Rres + (size_t)r2*N + cg);
                *(float2*)(C + (size_t)r1*N + cg) = make_float2(v00+ra.x, v01+ra.y);
                *(float2*)(C + (size_t)r2*N + cg) = make_float2(v10+rb.x, v11+rb.y);
            } else {
                // proj-combine: scatter window token -> pixel, y = x + proj + cv2*ca*0.01
                float* Y = (float*)Cout_;
                int rr[2] = {r1, r2};
                float vv[2][2] = {{v00, v01}, {v10, v11}};
                #pragma unroll
                for (int q = 0; q < 2; q++) {
                    int t = rr[q];
                    int n = t & 255, win = t >> 8;
                    int b = win >> 6, wl = win & 63;
                    int hh = ((wl >> 3) << 4) + (n >> 4);
                    int ww = ((wl & 7) << 4) + (n & 15);
                    int oh = (hh + SSc) & 127, ow = (ww + SSc) & 127;
                    size_t p = (size_t)((b*Hc + oh)*Wc + ow);
                    float2 xv = *(const float2*)(xres + p*Cc + cg);
                    float2 cav = *(const float2*)(cab + b*Cc + cg);
                    float2 cvv = __bfloat1622float2(*(const __nv_bfloat162*)(cv2b + p*Cc + cg));
                    *(float2*)(Y + p*Cc + cg) = make_float2(
                        xv.x + vv[q][0] + cvv.x*cav.x*0.01f,
                        xv.y + vv[q][1] + cvv.y*cav.y*0.01f);
                }
            }
        }
    }
}

// ---------------- 3x3 conv (implicit GEMM, cp.async + ldmatrix) --------------
// Block: one image row (128 pixels) x 64 output channels. MODE 0 plain/1 gelu.
template<int MODE>
__global__ __launch_bounds__(256, 2) void mma_conv(
        const bf16* __restrict__ X, const bf16* __restrict__ Wt,
        const float* __restrict__ bias, bf16* __restrict__ Y,
        int Cin, int Cout) {
    __shared__ __align__(16) bf16 As[2][128*AP];
    __shared__ __align__(16) bf16 Bs[2][32*BP2];
    int bi = blockIdx.x;
    int b = bi >> 7, h = bi & 127;
    int n0 = blockIdx.y * 64;
    int tid = threadIdx.x;
    int warp = tid >> 5, lane = tid & 31;
    int wm = warp & 3, wn = warp >> 2;
    int g = lane >> 2, tg = lane & 3;
    int ck = Cin >> 5;
    int nk = 9 * ck;

    auto loadA = [&](bf16* dst, int chunk) {
        int tap = chunk / ck, cc = chunk - tap*ck;
        int ci0 = cc * 32;
        int dh = tap/3 - 1, dw = tap%3 - 1;
        int ih = h + dh;
        bool rowok = (ih >= 0 && ih < Hc);
        int ihc = min(max(ih, 0), Hc-1);
        #pragma unroll
        for (int i = 0; i < 2; i++) {
            int idx = tid + i*256;
            int r = idx >> 2, kc = idx & 3;
            int iw = r + dw;
            int sz = (rowok && iw >= 0 && iw < Wc) ? 16 : 0;
            int iwc = min(max(iw, 0), Wc-1);
            const bf16* src = X + ((size_t)((b*Hc + ihc)*Wc + iwc))*Cin + ci0 + kc*8;
            CP16Z((uint32_t)__cvta_generic_to_shared(dst + r*AP + kc*8), src, sz);
        }
    };
    auto loadB = [&](bf16* dst, int chunk) {
        int tap = chunk / ck, cc = chunk - tap*ck;
        int ci0 = cc * 32;
        int k = tid >> 3, nc = tid & 7;
        CP16((uint32_t)__cvta_generic_to_shared(dst + k*BP2 + nc*8),
             Wt + (size_t)(tap*Cin + ci0 + k)*Cout + n0 + nc*8);
    };

    float acc[2][4][4];
    #pragma unroll
    for (int a = 0; a < 2; a++)
        #pragma unroll
        for (int bb = 0; bb < 4; bb++)
            #pragma unroll
            for (int c = 0; c < 4; c++) acc[a][bb][c] = 0.f;

    loadA(As[0], 0); loadB(Bs[0], 0);
    CP_COMMIT;
    for (int c = 0; c < nk; c++) {
        int nx = c + 1;
        if (nx < nk) { loadA(As[nx & 1], nx); loadB(Bs[nx & 1], nx); }
        CP_COMMIT;
        CP_WAIT1;
        __syncthreads();
        mma_chunk(As[c & 1], Bs[c & 1], wm, wn, lane, acc);
        __syncthreads();
    }

    #pragma unroll
    for (int mi = 0; mi < 2; mi++) {
        #pragma unroll
        for (int nj = 0; nj < 4; nj++) {
            int p1 = (b*Hc + h)*Wc + wm*32 + mi*16 + g;
            int p2 = p1 + 8;
            int cg = n0 + wn*32 + nj*8 + tg*2;
            float b0 = bias[cg], b1 = bias[cg+1];
            float v00 = acc[mi][nj][0] + b0, v01 = acc[mi][nj][1] + b1;
            float v10 = acc[mi][nj][2] + b0, v11 = acc[mi][nj][3] + b1;
            if (MODE == 1) {
                v00 = gelu_exact(v00); v01 = gelu_exact(v01);
                v10 = gelu_exact(v10); v11 = gelu_exact(v11);
            }
            *(__nv_bfloat162*)(Y + (size_t)p1*Cout + cg) = __floats2bfloat162_rn(v00, v01);
            *(__nv_bfloat162*)(Y + (size_t)p2*Cout + cg) = __floats2bfloat162_rn(v10, v11);
        }
    }
}

// ---------------- pool + channel attention -----------------------------------
__global__ void pool_kernel(const bf16* __restrict__ cv2b, float* __restrict__ pp) {
    int blk = blockIdx.x;
    int b = blk >> 6, chunk = blk & 63;
    int c = threadIdx.x;
    float s = 0.f;
    int base = b*16384 + chunk*256;
    for (int p = 0; p < 256; p++) s += __bfloat162float(cv2b[(size_t)(base + p)*Cc + c]);
    pp[blk*Cc + c] = s;
}

__global__ void ca_kernel(const float* __restrict__ pp,
                          const float* __restrict__ w1, const float* __restrict__ b1,
                          const float* __restrict__ w2, const float* __restrict__ b2,
                          float* __restrict__ ca) {
    __shared__ float pooled[Bc*Cc];
    __shared__ float t1[Bc*6];
    int tid = threadIdx.x;
    for (int i = tid; i < Bc*Cc; i += 256) {
        int b = i / Cc, c = i % Cc;
        float s = 0.f;
        for (int j = 0; j < 64; j++) s += pp[(b*64 + j)*Cc + c];
        pooled[i] = s * (1.f/16384.f);
    }
    __syncthreads();
    if (tid < Bc*6) {
        int b = tid / 6, j = tid % 6;
        float s = b1[j];
        for (int c = 0; c < Cc; c++) s += pooled[b*Cc + c] * w1[c*6 + j];
        t1[tid] = fmaxf(s, 0.f);
    }
    __syncthreads();
    for (int i = tid; i < Bc*Cc; i += 256) {
        int b = i / Cc, c = i % Cc;
        float s = b2[c];
        #pragma unroll
        for (int j = 0; j < 6; j++) s += t1[b*6 + j] * w2[j*Cc + c];
        ca[i] = 1.f / (1.f + expf(-s));
    }
}

// ---------------- flash window attention (fp32 smem K/V, packed f32x2) -------
__global__ __launch_bounds__(256) void attn_kernel(
        const bf16* __restrict__ qkvb, const float* __restrict__ btT,
        const float* __restrict__ mask, bf16* __restrict__ out) {
    extern __shared__ float sm[];
    float* Ks = sm;             // 256*32 fp32
    float* Vs = sm + Nc*HDc;
    int win = blockIdx.x, h = blockIdx.y;
    int n = threadIdx.x;
    // fill K/V (convert bf16 -> fp32)
    #pragma unroll
    for (int it = 0; it < 4; it++) {
        int item = n + it*256;          // 1024 items = row*4 + quad
        int row = item >> 2, c4 = item & 3;
        const uint4* kp = (const uint4*)(qkvb + ((size_t)(win*Nc + row))*576 + 192 + h*HDc) + c4;
        const uint4* vp = (const uint4*)(qkvb + ((size_t)(win*Nc + row))*576 + 384 + h*HDc) + c4;
        uint4 ku = *kp, vu = *vp;
        float2* kd = (float2*)(Ks + row*HDc + c4*8);
        float2* vd = (float2*)(Vs + row*HDc + c4*8);
        kd[0] = __bfloat1622float2(*(__nv_bfloat162*)&ku.x);
        kd[1] = __bfloat1622float2(*(__nv_bfloat162*)&ku.y);
        kd[2] = __bfloat1622float2(*(__nv_bfloat162*)&ku.z);
        kd[3] = __bfloat1622float2(*(__nv_bfloat162*)&ku.w);
        vd[0] = __bfloat1622float2(*(__nv_bfloat162*)&vu.x);
        vd[1] = __bfloat1622float2(*(__nv_bfloat162*)&vu.y);
        vd[2] = __bfloat1622float2(*(__nv_bfloat162*)&vu.z);
        vd[3] = __bfloat1622float2(*(__nv_bfloat162*)&vu.w);
    }
    // load Q (packed f32x2, pre-scaled)
    u64t q2[16];
    {
        const uint4* qp = (const uint4*)(qkvb + ((size_t)(win*Nc + n))*576 + h*HDc);
        #pragma unroll
        for (int i = 0; i < 4; i++) {
            uint4 u = qp[i];
            float2 f0 = __bfloat1622float2(*(__nv_bfloat162*)&u.x);
            float2 f1 = __bfloat1622float2(*(__nv_bfloat162*)&u.y);
            float2 f2 = __bfloat1622float2(*(__nv_bfloat162*)&u.z);
            float2 f3 = __bfloat1622float2(*(__nv_bfloat162*)&u.w);
            q2[4*i+0] = pk2(f0.x*ATT_SCALE, f0.y*ATT_SCALE);
            q2[4*i+1] = pk2(f1.x*ATT_SCALE, f1.y*ATT_SCALE);
            q2[4*i+2] = pk2(f2.x*ATT_SCALE, f2.y*ATT_SCALE);
            q2[4*i+3] = pk2(f3.x*ATT_SCALE, f3.y*ATT_SCALE);
        }
    }
    __syncthreads();
    const float* brow = btT  + (size_t)h*Nc*Nc + n;
    const float* mrow = mask + (size_t)(win & 63)*Nc*Nc + n;
    float mx = -1e30f, l = 0.f;
    u64t acc2[16];
    #pragma unroll
    for (int i = 0; i < 16; i++) acc2[i] = 0ull;

    #pragma unroll 4
    for (int m = 0; m < Nc; m++) {
        float bm = brow[(size_t)m*Nc] + mrow[(size_t)m*Nc];
        const ulonglong2* kr = (const ulonglong2*)(Ks + m*HDc);
        u64t s2 = 0ull;
        #pragma unroll
        for (int i = 0; i < 8; i++) {
            ulonglong2 u = kr[i];
            s2 = fma2(q2[2*i],   u.x, s2);
            s2 = fma2(q2[2*i+1], u.y, s2);
        }
        float2 sp = upk2(s2);
        float s = sp.x + sp.y + bm;
        float newmx = fmaxf(mx, s);
        float sc = __expf(mx - newmx);
        float p  = __expf(s - newmx);
        l = l*sc + p;
        mx = newmx;
        u64t sc2 = pk2(sc, sc), p2 = pk2(p, p);
        const ulonglong2* vr = (const ulonglong2*)(Vs + m*HDc);
        #pragma unroll
        for (int i = 0; i < 8; i++) {
            ulonglong2 u = vr[i];
            acc2[2*i]   = fma2(acc2[2*i],   sc2, mul2(u.x, p2));
            acc2[2*i+1] = fma2(acc2[2*i+1], sc2, mul2(u.y, p2));
        }
    }
    float inv = 1.f / l;
    __nv_bfloat162* orow = (__nv_bfloat162*)(out + (size_t)(win*Nc + n)*Cc + h*HDc);
    #pragma unroll
    for (int i = 0; i < 16; i++) {
        float2 f = upk2(acc2[i]);
        orow[i] = __floats2bfloat162_rn(f.x*inv, f.y*inv);
    }
}

// ---------------- launch -----------------------------------------------------
extern "C" void kernel_launch(void* const* d_in, const int* in_sizes, int n_in,
                              void* d_out, int out_size) {
    const float* x     = (const float*)d_in[0];
    const float* qkv_w = (const float*)d_in[1];
    const float* qkv_b = (const float*)d_in[2];
    const float* proj_w= (const float*)d_in[3];
    const float* proj_b= (const float*)d_in[4];
    const float* rpb   = (const float*)d_in[5];
    const float* n1w   = (const float*)d_in[6];
    const float* n1b   = (const float*)d_in[7];
    const float* n2w   = (const float*)d_in[8];
    const float* n2b   = (const float*)d_in[9];
    const float* c1w   = (const float*)d_in[10];
    const float* c1b   = (const float*)d_in[11];
    const float* c2w   = (const float*)d_in[12];
    const float* c2b   = (const float*)d_in[13];
    const float* ca1w  = (const float*)d_in[14];
    const float* ca1b  = (const float*)d_in[15];
    const float* ca2w  = (const float*)d_in[16];
    const float* ca2b  = (const float*)d_in[17];
    const float* fc1w  = (const float*)d_in[18];
    const float* fc1b  = (const float*)d_in[19];
    const float* fc2w  = (const float*)d_in[20];
    const float* fc2b  = (const float*)d_in[21];
    const int*   rpi   = (const int*)d_in[22];
    const float* amask = (const float*)d_in[23];
    float* out = (float*)d_out;

    bf16 *xnb, *qkvb, *atb, *cv1b, *cv2b, *ynb, *hb;
    bf16 *wqkv, *wproj, *wfc1, *wfc2, *wc1, *wc2;
    float *y, *pp, *cab, *btT;
    cudaGetSymbolAddress((void**)&xnb,  g_xnb);
    cudaGetSymbolAddress((void**)&qkvb, g_qkvb);
    cudaGetSymbolAddress((void**)&atb,  g_atb);
    cudaGetSymbolAddress((void**)&cv1b, g_cv1b);
    cudaGetSymbolAddress((void**)&cv2b, g_cv2b);
    cudaGetSymbolAddress((void**)&y,    g_y);
    cudaGetSymbolAddress((void**)&ynb,  g_ynb);
    cudaGetSymbolAddress((void**)&hb,   g_hb);
    cudaGetSymbolAddress((void**)&pp,   g_pp);
    cudaGetSymbolAddress((void**)&cab,  g_ca);
    cudaGetSymbolAddress((void**)&btT,  g_btT);
    cudaGetSymbolAddress((void**)&wqkv, g_wqkv);
    cudaGetSymbolAddress((void**)&wproj,g_wproj);
    cudaGetSymbolAddress((void**)&wfc1, g_wfc1);
    cudaGetSymbolAddress((void**)&wfc2, g_wfc2);
    cudaGetSymbolAddress((void**)&wc1,  g_wc1);
    cudaGetSymbolAddress((void**)&wc2,  g_wc2);

    static bool attr_set = false;
    if (!attr_set) {
        cudaFuncSetAttribute(attn_kernel, cudaFuncAttributeMaxDynamicSharedMemorySize,
                             2*Nc*HDc*sizeof(float));
        attr_set = true;
    }

    // weight converts + bias table
    f2b_kernel<<<(Cc*3*Cc + 255)/256, 256>>>(qkv_w, wqkv, Cc*3*Cc);
    f2b_kernel<<<(Cc*Cc + 255)/256, 256>>>(proj_w, wproj, Cc*Cc);
    f2b_kernel<<<(Cc*4*Cc + 255)/256, 256>>>(fc1w, wfc1, Cc*4*Cc);
    f2b_kernel<<<(4*Cc*Cc + 255)/256, 256>>>(fc2w, wfc2, 4*Cc*Cc);
    f2b_kernel<<<(9*Cc*64 + 255)/256, 256>>>(c1w, wc1, 9*Cc*64);
    f2b_kernel<<<(9*64*Cc + 255)/256, 256>>>(c2w, wc2, 9*64*Cc);
    biasT_kernel<<<(NHc*Nc*Nc + 255)/256, 256>>>(rpb, rpi, btT);

    // LN1
    ln_kernel<<<NPIX/8, 256>>>(x, n1w, n1b, xnb);
    // conv branch
    mma_conv<1><<<dim3(Bc*Hc, 1), 256>>>(xnb, wc1, c1b, cv1b, Cc, 64);
    mma_conv<0><<<dim3(Bc*Hc, 3), 256>>>(cv1b, wc2, c2b, cv2b, 64, Cc);
    pool_kernel<<<Bc*64, Cc>>>(cv2b, pp);
    ca_kernel<<<1, 256>>>(pp, ca1w, ca1b, ca2w, ca2b, cab);
    // attention branch (gather fused into qkv A-load)
    mma_gemm<0, 1><<<dim3(NPIX/128, 9), 256>>>(xnb, wqkv, qkv_b, qkvb,
                                               nullptr, nullptr, nullptr, nullptr, Cc, 3*Cc);
    attn_kernel<<<dim3(256, NHc), 256, 2*Nc*HDc*sizeof(float)>>>(qkvb, btT, amask, atb);
    // proj + window-reverse + residual combine fused
    mma_gemm<3, 0><<<dim3(NPIX/128, 3), 256>>>(atb, wproj, proj_b, y,
                                               nullptr, x, cv2b, cab, Cc, Cc);
    // MLP
    ln_kernel<<<NPIX/8, 256>>>(y, n2w, n2b, ynb);
    mma_gemm<1, 0><<<dim3(NPIX/128, 12), 256>>>(ynb, wfc1, fc1b, hb,
                                                nullptr, nullptr, nullptr, nullptr, Cc, 4*Cc);
    mma_gemm<2, 0><<<dim3(NPIX/128, 3), 256>>>(hb, wfc2, fc2b, out,
                                               y, nullptr, nullptr, nullptr, 4*Cc, Cc);
}

// round 5
// speedup vs baseline: 6.2695x; 1.4431x over previous
#include <cuda_runtime.h>
#include <cuda_bf16.h>
#include <math.h>
#include <stdint.h>

typedef __nv_bfloat16 bf16;

#define Bc 4
#define Hc 128
#define Wc 128
#define Cc 192
#define NHc 6
#define WSc 16
#define SSc 8
#define Nc 256
#define HDc 32
#define NPIX (Bc*Hc*Wc)            // 65536
#define ATT_SCALE 0.17677669529663687f

#define AP 40       // A smem row stride (bf16 elems)
#define BP2 72      // B smem row stride
#define QP 40       // attention smem row stride (80B: conflict-free ldmatrix)

// ---------------- scratch (device globals) -----------------------------------
__device__ bf16  g_xnb [NPIX*Cc];
__device__ bf16  g_qkvb[(size_t)NPIX*3*Cc];
__device__ bf16  g_atb [NPIX*Cc];
__device__ bf16  g_cv1b[NPIX*64];
__device__ bf16  g_cv2b[NPIX*Cc];
__device__ float g_y   [NPIX*Cc];
__device__ bf16  g_ynb [NPIX*Cc];
__device__ bf16  g_hb  [(size_t)NPIX*4*Cc];
__device__ float g_pp  [Bc*64*Cc];
__device__ float g_ca  [Bc*Cc];
__device__ bf16  g_cbt [(size_t)NHc*64*Nc*Nc];   // combined bias+mask [h*64+wl][q][k]
__device__ bf16  g_wqkv [Cc*3*Cc];
__device__ bf16  g_wproj[Cc*Cc];
__device__ bf16  g_wfc1 [Cc*4*Cc];
__device__ bf16  g_wfc2 [4*Cc*Cc];
__device__ bf16  g_wc1  [9*Cc*64];
__device__ bf16  g_wc2  [9*64*Cc];

__device__ __forceinline__ float gelu_exact(float x) {
    return 0.5f * x * (1.f + erff(x * 0.70710678118654752f));
}

// ---------------- ptx helpers ------------------------------------------------
#define CP16(dst, src) asm volatile("cp.async.cg.shared.global [%0], [%1], 16;\n" :: "r"(dst), "l"(src))
#define CP16Z(dst, src, sz) asm volatile("cp.async.cg.shared.global [%0], [%1], 16, %2;\n" :: "r"(dst), "l"(src), "r"(sz))
#define CP_COMMIT asm volatile("cp.async.commit_group;\n")
#define CP_WAIT1  asm volatile("cp.async.wait_group 1;\n")

__device__ __forceinline__ void ldsm4(uint32_t* r, uint32_t a) {
    asm volatile("ldmatrix.sync.aligned.m8n8.x4.shared.b16 {%0,%1,%2,%3},[%4];"
        : "=r"(r[0]), "=r"(r[1]), "=r"(r[2]), "=r"(r[3]) : "r"(a));
}
__device__ __forceinline__ void ldsm4t(uint32_t* r, uint32_t a) {
    asm volatile("ldmatrix.sync.aligned.m8n8.x4.trans.shared.b16 {%0,%1,%2,%3},[%4];"
        : "=r"(r[0]), "=r"(r[1]), "=r"(r[2]), "=r"(r[3]) : "r"(a));
}
__device__ __forceinline__ void mma_bf16(float* c, const uint32_t* a, const uint32_t* b) {
    asm volatile(
        "mma.sync.aligned.m16n8k16.row.col.f32.bf16.bf16.f32 "
        "{%0,%1,%2,%3}, {%4,%5,%6,%7}, {%8,%9}, {%0,%1,%2,%3};\n"
        : "+f"(c[0]), "+f"(c[1]), "+f"(c[2]), "+f"(c[3])
        : "r"(a[0]), "r"(a[1]), "r"(a[2]), "r"(a[3]), "r"(b[0]), "r"(b[1]));
}
__device__ __forceinline__ uint32_t pkbf2(float a, float b) {
    __nv_bfloat162 t = __floats2bfloat162_rn(a, b);
    return *(uint32_t*)&t;
}

// ---------------- small converts ---------------------------------------------
__global__ void f2b_kernel(const float* __restrict__ a, bf16* __restrict__ o, int n) {
    int i = blockIdx.x * 256 + threadIdx.x;
    if (i < n) o[i] = __float2bfloat16(a[i]);
}
// combined bias+mask table: cbt[(h*64+wl)][q][k] = rpb[rpi[q,k], h] + mask[wl][q][k]
__global__ void cbt_kernel(const float* __restrict__ rpb, const int* __restrict__ rpi,
                           const float* __restrict__ amask, bf16* __restrict__ cbt) {
    size_t idx = (size_t)blockIdx.x * 256 + threadIdx.x;
    int hw = idx >> 16;
    int h = hw >> 6, wl = hw & 63;
    int qk = idx & 65535;
    cbt[idx] = __float2bfloat16(rpb[rpi[qk]*NHc + h] + amask[(size_t)wl*65536 + qk]);
}

// ---------------- LayerNorm: warp per token ----------------------------------
__global__ __launch_bounds__(256) void ln_kernel(
        const float* __restrict__ x, const float* __restrict__ g,
        const float* __restrict__ b, bf16* __restrict__ out) {
    int t = (blockIdx.x * 256 + threadIdx.x) >> 5;
    int lane = threadIdx.x & 31;
    const float* row = x + (size_t)t * Cc;
    float v[6], s = 0.f, ss = 0.f;
    #pragma unroll
    for (int i = 0; i < 6; i++) {
        v[i] = row[i*32 + lane];
        s += v[i]; ss += v[i]*v[i];
    }
    #pragma unroll
    for (int o = 16; o; o >>= 1) {
        s  += __shfl_xor_sync(0xffffffffu, s, o);
        ss += __shfl_xor_sync(0xffffffffu, ss, o);
    }
    float m = s * (1.f/Cc);
    float inv = rsqrtf(ss * (1.f/Cc) - m*m + 1e-5f);
    #pragma unroll
    for (int i = 0; i < 6; i++) {
        int c = i*32 + lane;
        out[(size_t)t*Cc + c] = __float2bfloat16((v[i] - m)*inv*g[c] + b[c]);
    }
}

// ---------------- MMA compute for one 128x64x32 chunk ------------------------
__device__ __forceinline__ void mma_chunk(const bf16* As, const bf16* Bs,
        int wm, int wn, int lane, float acc[2][4][4]) {
    #pragma unroll
    for (int kk = 0; kk < 32; kk += 16) {
        uint32_t af[2][4], bq[2][4];
        #pragma unroll
        for (int mi = 0; mi < 2; mi++) {
            int r = wm*32 + mi*16 + (lane & 15);
            int kofs = kk + ((lane >> 4) << 3);
            ldsm4(af[mi], (uint32_t)__cvta_generic_to_shared(As + r*AP + kofs));
        }
        #pragma unroll
        for (int nh = 0; nh < 2; nh++) {
            int krow = kk + (lane & 7) + (lane & 8);
            int ncol = wn*32 + nh*16 + ((lane >> 4) << 3);
            ldsm4t(bq[nh], (uint32_t)__cvta_generic_to_shared(Bs + krow*BP2 + ncol));
        }
        #pragma unroll
        for (int mi = 0; mi < 2; mi++) {
            mma_bf16(acc[mi][0], af[mi], &bq[0][0]);
            mma_bf16(acc[mi][1], af[mi], &bq[0][2]);
            mma_bf16(acc[mi][2], af[mi], &bq[1][0]);
            mma_bf16(acc[mi][3], af[mi], &bq[1][2]);
        }
    }
}

// ---------------- GEMM: MODE 0 bf16; 1 gelu bf16; 2 fp32+res; 3 proj-combine -
template<int MODE, int GATHER>
__global__ __launch_bounds__(256, 2) void mma_gemm(
        const bf16* __restrict__ A, const bf16* __restrict__ W,
        const float* __restrict__ bias, void* __restrict__ Cout_,
        const float* __restrict__ Rres, const float* __restrict__ xres,
        const bf16* __restrict__ cv2b, const float* __restrict__ cab,
        int K, int N) {
    __shared__ __align__(16) bf16 As[2][128*AP];
    __shared__ __align__(16) bf16 Bs[2][32*BP2];
    int tid = threadIdx.x;
    int m0 = blockIdx.x * 128, n0 = blockIdx.y * 64;
    int warp = tid >> 5, lane = tid & 31;
    int wm = warp & 3, wn = warp >> 2;
    int g = lane >> 2, tg = lane & 3;
    int nk = K >> 5;

    auto loadA = [&](bf16* dst, int k0) {
        #pragma unroll
        for (int i = 0; i < 2; i++) {
            int idx = tid + i*256;
            int r = idx >> 2, kc = idx & 3;
            const bf16* src;
            if (GATHER) {
                int t = m0 + r; int n = t & 255, win = t >> 8;
                int b = win >> 6, wl = win & 63;
                int hh = (((wl >> 3) << 4) + (n >> 4) + SSc) & 127;
                int ww = (((wl & 7) << 4) + (n & 15) + SSc) & 127;
                src = A + ((size_t)((b*Hc + hh)*Wc + ww))*K + k0 + kc*8;
            } else {
                src = A + (size_t)(m0 + r)*K + k0 + kc*8;
            }
            CP16((uint32_t)__cvta_generic_to_shared(dst + r*AP + kc*8), src);
        }
    };
    auto loadB = [&](bf16* dst, int k0) {
        int k = tid >> 3, nc = tid & 7;
        CP16((uint32_t)__cvta_generic_to_shared(dst + k*BP2 + nc*8),
             W + (size_t)(k0 + k)*N + n0 + nc*8);
    };

    float acc[2][4][4];
    #pragma unroll
    for (int a = 0; a < 2; a++)
        #pragma unroll
        for (int b = 0; b < 4; b++)
            #pragma unroll
            for (int c = 0; c < 4; c++) acc[a][b][c] = 0.f;

    loadA(As[0], 0); loadB(Bs[0], 0);
    CP_COMMIT;
    for (int c = 0; c < nk; c++) {
        int nx = c + 1;
        if (nx < nk) { loadA(As[nx & 1], nx*32); loadB(Bs[nx & 1], nx*32); }
        CP_COMMIT;
        CP_WAIT1;
        __syncthreads();
        mma_chunk(As[c & 1], Bs[c & 1], wm, wn, lane, acc);
        __syncthreads();
    }

    #pragma unroll
    for (int mi = 0; mi < 2; mi++) {
        #pragma unroll
        for (int nj = 0; nj < 4; nj++) {
            int r1 = m0 + wm*32 + mi*16 + g;
            int r2 = r1 + 8;
            int cg = n0 + wn*32 + nj*8 + tg*2;
            float b0 = bias[cg], b1 = bias[cg+1];
            float v00 = acc[mi][nj][0] + b0, v01 = acc[mi][nj][1] + b1;
            float v10 = acc[mi][nj][2] + b0, v11 = acc[mi][nj][3] + b1;
            if (MODE == 0) {
                bf16* C = (bf16*)Cout_;
                *(__nv_bfloat162*)(C + (size_t)r1*N + cg) = __floats2bfloat162_rn(v00, v01);
                *(__nv_bfloat162*)(C + (size_t)r2*N + cg) = __floats2bfloat162_rn(v10, v11);
            } else if (MODE == 1) {
                bf16* C = (bf16*)Cout_;
                *(__nv_bfloat162*)(C + (size_t)r1*N + cg) =
                    __floats2bfloat162_rn(gelu_exact(v00), gelu_exact(v01));
                *(__nv_bfloat162*)(C + (size_t)r2*N + cg) =
                    __floats2bfloat162_rn(gelu_exact(v10), gelu_exact(v11));
            } else if (MODE == 2) {
                float* C = (float*)Cout_;
                float2 ra = *(const float2*)(Rres + (size_t)r1*N + cg);
                float2 rb = *(const float2*)(Rres + (size_t)r2*N + cg);
                *(float2*)(C + (size_t)r1*N + cg) = make_float2(v00+ra.x, v01+ra.y);
                *(float2*)(C + (size_t)r2*N + cg) = make_float2(v10+rb.x, v11+rb.y);
            } else {
                float* Y = (float*)Cout_;
                int rr[2] = {r1, r2};
                float vv[2][2] = {{v00, v01}, {v10, v11}};
                #pragma unroll
                for (int q = 0; q < 2; q++) {
                    int t = rr[q];
                    int n = t & 255, win = t >> 8;
                    int b = win >> 6, wl = win & 63;
                    int hh = ((wl >> 3) << 4) + (n >> 4);
                    int ww = ((wl & 7) << 4) + (n & 15);
                    int oh = (hh + SSc) & 127, ow = (ww + SSc) & 127;
                    size_t p = (size_t)((b*Hc + oh)*Wc + ow);
                    float2 xv = *(const float2*)(xres + p*Cc + cg);
                    float2 cav = *(const float2*)(cab + b*Cc + cg);
                    float2 cvv = __bfloat1622float2(*(const __nv_bfloat162*)(cv2b + p*Cc + cg));
                    *(float2*)(Y + p*Cc + cg) = make_float2(
                        xv.x + vv[q][0] + cvv.x*cav.x*0.01f,
                        xv.y + vv[q][1] + cvv.y*cav.y*0.01f);
                }
            }
        }
    }
}

// ---------------- 3x3 conv (implicit GEMM) ------------------------------------
template<int MODE>
__global__ __launch_bounds__(256, 2) void mma_conv(
        const bf16* __restrict__ X, const bf16* __restrict__ Wt,
        const float* __restrict__ bias, bf16* __restrict__ Y,
        int Cin, int Cout) {
    __shared__ __align__(16) bf16 As[2][128*AP];
    __shared__ __align__(16) bf16 Bs[2][32*BP2];
    int bi = blockIdx.x;
    int b = bi >> 7, h = bi & 127;
    int n0 = blockIdx.y * 64;
    int tid = threadIdx.x;
    int warp = tid >> 5, lane = tid & 31;
    int wm = warp & 3, wn = warp >> 2;
    int g = lane >> 2, tg = lane & 3;
    int ck = Cin >> 5;
    int nk = 9 * ck;

    auto loadA = [&](bf16* dst, int chunk) {
        int tap = chunk / ck, cc = chunk - tap*ck;
        int ci0 = cc * 32;
        int dh = tap/3 - 1, dw = tap%3 - 1;
        int ih = h + dh;
        bool rowok = (ih >= 0 && ih < Hc);
        int ihc = min(max(ih, 0), Hc-1);
        #pragma unroll
        for (int i = 0; i < 2; i++) {
            int idx = tid + i*256;
            int r = idx >> 2, kc = idx & 3;
            int iw = r + dw;
            int sz = (rowok && iw >= 0 && iw < Wc) ? 16 : 0;
            int iwc = min(max(iw, 0), Wc-1);
            const bf16* src = X + ((size_t)((b*Hc + ihc)*Wc + iwc))*Cin + ci0 + kc*8;
            CP16Z((uint32_t)__cvta_generic_to_shared(dst + r*AP + kc*8), src, sz);
        }
    };
    auto loadB = [&](bf16* dst, int chunk) {
        int tap = chunk / ck, cc = chunk - tap*ck;
        int ci0 = cc * 32;
        int k = tid >> 3, nc = tid & 7;
        CP16((uint32_t)__cvta_generic_to_shared(dst + k*BP2 + nc*8),
             Wt + (size_t)(tap*Cin + ci0 + k)*Cout + n0 + nc*8);
    };

    float acc[2][4][4];
    #pragma unroll
    for (int a = 0; a < 2; a++)
        #pragma unroll
        for (int bb = 0; bb < 4; bb++)
            #pragma unroll
            for (int c = 0; c < 4; c++) acc[a][bb][c] = 0.f;

    loadA(As[0], 0); loadB(Bs[0], 0);
    CP_COMMIT;
    for (int c = 0; c < nk; c++) {
        int nx = c + 1;
        if (nx < nk) { loadA(As[nx & 1], nx); loadB(Bs[nx & 1], nx); }
        CP_COMMIT;
        CP_WAIT1;
        __syncthreads();
        mma_chunk(As[c & 1], Bs[c & 1], wm, wn, lane, acc);
        __syncthreads();
    }

    #pragma unroll
    for (int mi = 0; mi < 2; mi++) {
        #pragma unroll
        for (int nj = 0; nj < 4; nj++) {
            int p1 = (b*Hc + h)*Wc + wm*32 + mi*16 + g;
            int p2 = p1 + 8;
            int cg = n0 + wn*32 + nj*8 + tg*2;
            float b0 = bias[cg], b1 = bias[cg+1];
            float v00 = acc[mi][nj][0] + b0, v01 = acc[mi][nj][1] + b1;
            float v10 = acc[mi][nj][2] + b0, v11 = acc[mi][nj][3] + b1;
            if (MODE == 1) {
                v00 = gelu_exact(v00); v01 = gelu_exact(v01);
                v10 = gelu_exact(v10); v11 = gelu_exact(v11);
            }
            *(__nv_bfloat162*)(Y + (size_t)p1*Cout + cg) = __floats2bfloat162_rn(v00, v01);
            *(__nv_bfloat162*)(Y + (size_t)p2*Cout + cg) = __floats2bfloat162_rn(v10, v11);
        }
    }
}

// ---------------- pool + channel attention -----------------------------------
__global__ void pool_kernel(const bf16* __restrict__ cv2b, float* __restrict__ pp) {
    int blk = blockIdx.x;
    int b = blk >> 6, chunk = blk & 63;
    int c = threadIdx.x;
    float s = 0.f;
    int base = b*16384 + chunk*256;
    for (int p = 0; p < 256; p++) s += __bfloat162float(cv2b[(size_t)(base + p)*Cc + c]);
    pp[blk*Cc + c] = s;
}

__global__ void ca_kernel(const float* __restrict__ pp,
                          const float* __restrict__ w1, const float* __restrict__ b1,
                          const float* __restrict__ w2, const float* __restrict__ b2,
                          float* __restrict__ ca) {
    __shared__ float pooled[Bc*Cc];
    __shared__ float t1[Bc*6];
    int tid = threadIdx.x;
    for (int i = tid; i < Bc*Cc; i += 256) {
        int b = i / Cc, c = i % Cc;
        float s = 0.f;
        for (int j = 0; j < 64; j++) s += pp[(b*64 + j)*Cc + c];
        pooled[i] = s * (1.f/16384.f);
    }
    __syncthreads();
    if (tid < Bc*6) {
        int b = tid / 6, j = tid % 6;
        float s = b1[j];
        for (int c = 0; c < Cc; c++) s += pooled[b*Cc + c] * w1[c*6 + j];
        t1[tid] = fmaxf(s, 0.f);
    }
    __syncthreads();
    for (int i = tid; i < Bc*Cc; i += 256) {
        int b = i / Cc, c = i % Cc;
        float s = b2[c];
        #pragma unroll
        for (int j = 0; j < 6; j++) s += t1[b*6 + j] * w2[j*Cc + c];
        ca[i] = 1.f / (1.f + expf(-s));
    }
}

// ---------------- flash window attention via tensor-core MMA ------------------
// Block = (window, head). 8 warps x 32 query rows. K in chunks of 32, online softmax.
__global__ __launch_bounds__(256) void attn_mma(
        const bf16* __restrict__ qkvb, const bf16* __restrict__ cbt,
        bf16* __restrict__ out) {
    extern __shared__ __align__(16) bf16 smA[];
    bf16* Qs = smA;              // 256 x 32, stride QP
    bf16* Ks = smA + 256*QP;
    bf16* Vs = smA + 2*256*QP;
    int win = blockIdx.x, h = blockIdx.y;
    int tid = threadIdx.x;
    int warp = tid >> 5, lane = tid & 31;
    int g = lane >> 2, tg = lane & 3;
    int m0 = warp * 32;

    // stage Q/K/V rows (row = tid)
    {
        const uint4* src = (const uint4*)(qkvb + (size_t)(win*Nc + tid)*576 + h*HDc);
        uint4* qd = (uint4*)(Qs + tid*QP);
        uint4* kd = (uint4*)(Ks + tid*QP);
        uint4* vd = (uint4*)(Vs + tid*QP);
        #pragma unroll
        for (int i = 0; i < 4; i++) {
            qd[i] = src[i];
            kd[i] = src[i + 24];    // +192 elems = +24 uint4
            vd[i] = src[i + 48];    // +384 elems
        }
    }
    __syncthreads();

    // Q fragments (held in regs for whole kernel)
    uint32_t qf[2][2][4];
    #pragma unroll
    for (int mi = 0; mi < 2; mi++)
        #pragma unroll
        for (int ks = 0; ks < 2; ks++) {
            int r = m0 + mi*16 + (lane & 15);
            int kofs = ks*16 + ((lane >> 4) << 3);
            ldsm4(qf[mi][ks], (uint32_t)__cvta_generic_to_shared(Qs + r*QP + kofs));
        }

    const bf16* cb = cbt + ((size_t)(h*64 + (win & 63)) << 16);

    float mx[2][2], lsum[2][2];
    float o[2][4][4];
    #pragma unroll
    for (int mi = 0; mi < 2; mi++)
        #pragma unroll
        for (int rh = 0; rh < 2; rh++) { mx[mi][rh] = -1e30f; lsum[mi][rh] = 0.f; }
    #pragma unroll
    for (int mi = 0; mi < 2; mi++)
        #pragma unroll
        for (int nt = 0; nt < 4; nt++)
            #pragma unroll
            for (int e = 0; e < 4; e++) o[mi][nt][e] = 0.f;

    for (int c0 = 0; c0 < Nc; c0 += 32) {
        float s[2][4][4];
        #pragma unroll
        for (int mi = 0; mi < 2; mi++)
            #pragma unroll
            for (int nj = 0; nj < 4; nj++)
                #pragma unroll
                for (int e = 0; e < 4; e++) s[mi][nj][e] = 0.f;

        // ---- S = Q K^T over 32 keys
        #pragma unroll
        for (int ks = 0; ks < 2; ks++) {
            uint32_t kf[2][4];
            #pragma unroll
            for (int np = 0; np < 2; np++) {
                int n = c0 + np*16 + (lane & 7) + ((lane >> 4) << 3);
                int kc = ks*16 + ((lane >> 3) & 1)*8;
                ldsm4(kf[np], (uint32_t)__cvta_generic_to_shared(Ks + n*QP + kc));
            }
            #pragma unroll
            for (int mi = 0; mi < 2; mi++) {
                mma_bf16(s[mi][0], qf[mi][ks], &kf[0][0]);
                mma_bf16(s[mi][1], qf[mi][ks], &kf[0][2]);
                mma_bf16(s[mi][2], qf[mi][ks], &kf[1][0]);
                mma_bf16(s[mi][3], qf[mi][ks], &kf[1][2]);
            }
        }

        // ---- scale + bias/mask + online softmax
        #pragma unroll
        for (int mi = 0; mi < 2; mi++) {
            int row0 = m0 + mi*16 + g;
            #pragma unroll
            for (int nj = 0; nj < 4; nj++) {
                int col = c0 + nj*8 + tg*2;
                float2 b0 = __bfloat1622float2(*(const __nv_bfloat162*)(cb + (size_t)row0*Nc + col));
                float2 b1 = __bfloat1622float2(*(const __nv_bfloat162*)(cb + (size_t)(row0+8)*Nc + col));
                s[mi][nj][0] = s[mi][nj][0]*ATT_SCALE + b0.x;
                s[mi][nj][1] = s[mi][nj][1]*ATT_SCALE + b0.y;
                s[mi][nj][2] = s[mi][nj][2]*ATT_SCALE + b1.x;
                s[mi][nj][3] = s[mi][nj][3]*ATT_SCALE + b1.y;
            }
            #pragma unroll
            for (int rh = 0; rh < 2; rh++) {
                int e0 = rh*2;
                float m_ = fmaxf(fmaxf(s[mi][0][e0], s[mi][0][e0+1]),
                                 fmaxf(s[mi][1][e0], s[mi][1][e0+1]));
                m_ = fmaxf(m_, fmaxf(fmaxf(s[mi][2][e0], s[mi][2][e0+1]),
                                     fmaxf(s[mi][3][e0], s[mi][3][e0+1])));
                m_ = fmaxf(m_, __shfl_xor_sync(0xffffffffu, m_, 1));
                m_ = fmaxf(m_, __shfl_xor_sync(0xffffffffu, m_, 2));
                float newm = fmaxf(mx[mi][rh], m_);
                float sc = __expf(mx[mi][rh] - newm);
                mx[mi][rh] = newm;
                float ps = 0.f;
                #pragma unroll
                for (int nj = 0; nj < 4; nj++) {
                    float p0 = __expf(s[mi][nj][e0]   - newm);
                    float p1 = __expf(s[mi][nj][e0+1] - newm);
                    s[mi][nj][e0] = p0; s[mi][nj][e0+1] = p1;
                    ps += p0 + p1;
                }
                ps += __shfl_xor_sync(0xffffffffu, ps, 1);
                ps += __shfl_xor_sync(0xffffffffu, ps, 2);
                lsum[mi][rh] = lsum[mi][rh]*sc + ps;
                #pragma unroll
                for (int nt = 0; nt < 4; nt++) {
                    o[mi][nt][e0]   *= sc;
                    o[mi][nt][e0+1] *= sc;
                }
            }
        }

        // ---- O += P V
        #pragma unroll
        for (int ks2 = 0; ks2 < 2; ks2++) {
            uint32_t vf[2][4];
            int krow = c0 + ks2*16 + (lane & 7) + (lane & 8);
            #pragma unroll
            for (int dp = 0; dp < 2; dp++)
                ldsm4t(vf[dp], (uint32_t)__cvta_generic_to_shared(
                    Vs + krow*QP + dp*16 + ((lane >> 4) << 3)));
            #pragma unroll
            for (int mi = 0; mi < 2; mi++) {
                uint32_t af[4];
                af[0] = pkbf2(s[mi][2*ks2][0],   s[mi][2*ks2][1]);
                af[1] = pkbf2(s[mi][2*ks2][2],   s[mi][2*ks2][3]);
                af[2] = pkbf2(s[mi][2*ks2+1][0], s[mi][2*ks2+1][1]);
                af[3] = pkbf2(s[mi][2*ks2+1][2], s[mi][2*ks2+1][3]);
                mma_bf16(o[mi][0], af, &vf[0][0]);
                mma_bf16(o[mi][1], af, &vf[0][2]);
                mma_bf16(o[mi][2], af, &vf[1][0]);
                mma_bf16(o[mi][3], af, &vf[1][2]);
            }
        }
    }

    // ---- epilogue
    #pragma unroll
    for (int mi = 0; mi < 2; mi++) {
        #pragma unroll
        for (int rh = 0; rh < 2; rh++) {
            float inv = 1.f / lsum[mi][rh];
            int row = win*Nc + m0 + mi*16 + g + rh*8;
            bf16* orow = out + (size_t)row*Cc + h*HDc;
            #pragma unroll
            for (int nt = 0; nt < 4; nt++) {
                *(__nv_bfloat162*)(orow + nt*8 + tg*2) =
                    __floats2bfloat162_rn(o[mi][nt][rh*2]*inv, o[mi][nt][rh*2+1]*inv);
            }
        }
    }
}

// ---------------- launch -----------------------------------------------------
extern "C" void kernel_launch(void* const* d_in, const int* in_sizes, int n_in,
                              void* d_out, int out_size) {
    const float* x     = (const float*)d_in[0];
    const float* qkv_w = (const float*)d_in[1];
    const float* qkv_b = (const float*)d_in[2];
    const float* proj_w= (const float*)d_in[3];
    const float* proj_b= (const float*)d_in[4];
    const float* rpb   = (const float*)d_in[5];
    const float* n1w   = (const float*)d_in[6];
    const float* n1b   = (const float*)d_in[7];
    const float* n2w   = (const float*)d_in[8];
    const float* n2b   = (const float*)d_in[9];
    const float* c1w   = (const float*)d_in[10];
    const float* c1b   = (const float*)d_in[11];
    const float* c2w   = (const float*)d_in[12];
    const float* c2b   = (const float*)d_in[13];
    const float* ca1w  = (const float*)d_in[14];
    const float* ca1b  = (const float*)d_in[15];
    const float* ca2w  = (const float*)d_in[16];
    const float* ca2b  = (const float*)d_in[17];
    const float* fc1w  = (const float*)d_in[18];
    const float* fc1b  = (const float*)d_in[19];
    const float* fc2w  = (const float*)d_in[20];
    const float* fc2b  = (const float*)d_in[21];
    const int*   rpi   = (const int*)d_in[22];
    const float* amask = (const float*)d_in[23];
    float* out = (float*)d_out;

    bf16 *xnb, *qkvb, *atb, *cv1b, *cv2b, *ynb, *hb, *cbt;
    bf16 *wqkv, *wproj, *wfc1, *wfc2, *wc1, *wc2;
    float *y, *pp, *cab;
    cudaGetSymbolAddress((void**)&xnb,  g_xnb);
    cudaGetSymbolAddress((void**)&qkvb, g_qkvb);
    cudaGetSymbolAddress((void**)&atb,  g_atb);
    cudaGetSymbolAddress((void**)&cv1b, g_cv1b);
    cudaGetSymbolAddress((void**)&cv2b, g_cv2b);
    cudaGetSymbolAddress((void**)&y,    g_y);
    cudaGetSymbolAddress((void**)&ynb,  g_ynb);
    cudaGetSymbolAddress((void**)&hb,   g_hb);
    cudaGetSymbolAddress((void**)&pp,   g_pp);
    cudaGetSymbolAddress((void**)&cab,  g_ca);
    cudaGetSymbolAddress((void**)&cbt,  g_cbt);
    cudaGetSymbolAddress((void**)&wqkv, g_wqkv);
    cudaGetSymbolAddress((void**)&wproj,g_wproj);
    cudaGetSymbolAddress((void**)&wfc1, g_wfc1);
    cudaGetSymbolAddress((void**)&wfc2, g_wfc2);
    cudaGetSymbolAddress((void**)&wc1,  g_wc1);
    cudaGetSymbolAddress((void**)&wc2,  g_wc2);

    static bool attr_set = false;
    if (!attr_set) {
        cudaFuncSetAttribute(attn_mma, cudaFuncAttributeMaxDynamicSharedMemorySize,
                             3*256*QP*sizeof(bf16));
        attr_set = true;
    }

    // weight converts + combined bias/mask table
    f2b_kernel<<<(Cc*3*Cc + 255)/256, 256>>>(qkv_w, wqkv, Cc*3*Cc);
    f2b_kernel<<<(Cc*Cc + 255)/256, 256>>>(proj_w, wproj, Cc*Cc);
    f2b_kernel<<<(Cc*4*Cc + 255)/256, 256>>>(fc1w, wfc1, Cc*4*Cc);
    f2b_kernel<<<(4*Cc*Cc + 255)/256, 256>>>(fc2w, wfc2, 4*Cc*Cc);
    f2b_kernel<<<(9*Cc*64 + 255)/256, 256>>>(c1w, wc1, 9*Cc*64);
    f2b_kernel<<<(9*64*Cc + 255)/256, 256>>>(c2w, wc2, 9*64*Cc);
    cbt_kernel<<<NHc*64*Nc*Nc/256, 256>>>(rpb, rpi, amask, cbt);

    // LN1
    ln_kernel<<<NPIX/8, 256>>>(x, n1w, n1b, xnb);
    // conv branch
    mma_conv<1><<<dim3(Bc*Hc, 1), 256>>>(xnb, wc1, c1b, cv1b, Cc, 64);
    mma_conv<0><<<dim3(Bc*Hc, 3), 256>>>(cv1b, wc2, c2b, cv2b, 64, Cc);
    pool_kernel<<<Bc*64, Cc>>>(cv2b, pp);
    ca_kernel<<<1, 256>>>(pp, ca1w, ca1b, ca2w, ca2b, cab);
    // attention branch (gather fused into qkv A-load)
    mma_gemm<0, 1><<<dim3(NPIX/128, 9), 256>>>(xnb, wqkv, qkv_b, qkvb,
                                               nullptr, nullptr, nullptr, nullptr, Cc, 3*Cc);
    attn_mma<<<dim3(256, NHc), 256, 3*256*QP*sizeof(bf16)>>>(qkvb, cbt, atb);
    // proj + window-reverse + residual combine fused
    mma_gemm<3, 0><<<dim3(NPIX/128, 3), 256>>>(atb, wproj, proj_b, y,
                                               nullptr, x, cv2b, cab, Cc, Cc);
    // MLP
    ln_kernel<<<NPIX/8, 256>>>(y, n2w, n2b, ynb);
    mma_gemm<1, 0><<<dim3(NPIX/128, 12), 256>>>(ynb, wfc1, fc1b, hb,
                                                nullptr, nullptr, nullptr, nullptr, Cc, 4*Cc);
    mma_gemm<2, 0><<<dim3(NPIX/128, 3), 256>>>(hb, wfc2, fc2b, out,
                                               y, nullptr, nullptr, nullptr, 4*Cc, Cc);
}

// round 7
// speedup vs baseline: 6.9012x; 1.1008x over previous
#include <cuda_runtime.h>
#include <cuda_bf16.h>
#include <math.h>
#include <stdint.h>

typedef __nv_bfloat16 bf16;

#define Bc 4
#define Hc 128
#define Wc 128
#define Cc 192
#define NHc 6
#define WSc 16
#define SSc 8
#define Nc 256
#define HDc 32
#define NPIX (Bc*Hc*Wc)            // 65536
#define ATT_SCALE 0.17677669529663687f

#define AP 40       // A smem row stride (bf16 elems)
#define BP2 72      // B smem row stride
#define QP 40       // attention smem row stride

// ---------------- scratch (device globals) -----------------------------------
__device__ bf16  g_xnb [NPIX*Cc];
__device__ bf16  g_qkvb[(size_t)NPIX*3*Cc];
__device__ bf16  g_atb [NPIX*Cc];
__device__ bf16  g_cv1b[NPIX*64];
__device__ bf16  g_cv2b[NPIX*Cc];
__device__ float g_y   [NPIX*Cc];
__device__ bf16  g_ynb [NPIX*Cc];
__device__ bf16  g_hb  [(size_t)NPIX*4*Cc];
__device__ float g_pp  [Bc*64*Cc];
__device__ float g_ca  [Bc*Cc];
__device__ bf16  g_btb [NHc*Nc*Nc];        // per-head bias table [h][q][k] (786KB)
__device__ bf16  g_wqkv [Cc*3*Cc];
__device__ bf16  g_wproj[Cc*Cc];
__device__ bf16  g_wfc1 [Cc*4*Cc];
__device__ bf16  g_wfc2 [4*Cc*Cc];
__device__ bf16  g_wc1  [9*Cc*64];
__device__ bf16  g_wc2  [9*64*Cc];

__device__ __forceinline__ float gelu_exact(float x) {
    return 0.5f * x * (1.f + erff(x * 0.70710678118654752f));
}

// ---------------- ptx helpers ------------------------------------------------
#define CP16(dst, src) asm volatile("cp.async.cg.shared.global [%0], [%1], 16;\n" :: "r"(dst), "l"(src))
#define CP16Z(dst, src, sz) asm volatile("cp.async.cg.shared.global [%0], [%1], 16, %2;\n" :: "r"(dst), "l"(src), "r"(sz))
#define CP_COMMIT asm volatile("cp.async.commit_group;\n")
#define CP_WAITG1 asm volatile("cp.async.wait_group 1;\n")

__device__ __forceinline__ void ldsm4(uint32_t* r, uint32_t a) {
    asm volatile("ldmatrix.sync.aligned.m8n8.x4.shared.b16 {%0,%1,%2,%3},[%4];"
        : "=r"(r[0]), "=r"(r[1]), "=r"(r[2]), "=r"(r[3]) : "r"(a));
}
__device__ __forceinline__ void ldsm4t(uint32_t* r, uint32_t a) {
    asm volatile("ldmatrix.sync.aligned.m8n8.x4.trans.shared.b16 {%0,%1,%2,%3},[%4];"
        : "=r"(r[0]), "=r"(r[1]), "=r"(r[2]), "=r"(r[3]) : "r"(a));
}
__device__ __forceinline__ void mma_bf16(float* c, const uint32_t* a, const uint32_t* b) {
    asm volatile(
        "mma.sync.aligned.m16n8k16.row.col.f32.bf16.bf16.f32 "
        "{%0,%1,%2,%3}, {%4,%5,%6,%7}, {%8,%9}, {%0,%1,%2,%3};\n"
        : "+f"(c[0]), "+f"(c[1]), "+f"(c[2]), "+f"(c[3])
        : "r"(a[0]), "r"(a[1]), "r"(a[2]), "r"(a[3]), "r"(b[0]), "r"(b[1]));
}
__device__ __forceinline__ uint32_t pkbf2(float a, float b) {
    __nv_bfloat162 t = __floats2bfloat162_rn(a, b);
    return *(uint32_t*)&t;
}

// ---------------- batched weight convert --------------------------------------
#define S0 110592
#define S1 36864
#define S2 147456
#define S3 147456
#define S4 110592
#define S5 110592
#define STOT (S0+S1+S2+S3+S4+S5)   // 663552
__global__ void f2b_all(const float* __restrict__ a0, const float* __restrict__ a1,
                        const float* __restrict__ a2, const float* __restrict__ a3,
                        const float* __restrict__ a4, const float* __restrict__ a5,
                        bf16* o0, bf16* o1, bf16* o2, bf16* o3, bf16* o4, bf16* o5) {
    int i = blockIdx.x * 256 + threadIdx.x;
    if (i >= STOT) return;
    if (i < S0)                { o0[i] = __float2bfloat16(a0[i]); return; }
    i -= S0;
    if (i < S1)                { o1[i] = __float2bfloat16(a1[i]); return; }
    i -= S1;
    if (i < S2)                { o2[i] = __float2bfloat16(a2[i]); return; }
    i -= S2;
    if (i < S3)                { o3[i] = __float2bfloat16(a3[i]); return; }
    i -= S3;
    if (i < S4)                { o4[i] = __float2bfloat16(a4[i]); return; }
    i -= S4;
    o5[i] = __float2bfloat16(a5[i]);
}

// per-head bias table: btb[h][q][k] = rpb[rpi[q*256+k], h]
__global__ void btb_kernel(const float* __restrict__ rpb, const int* __restrict__ rpi,
                           bf16* __restrict__ btb) {
    int idx = blockIdx.x * 256 + threadIdx.x;
    int h = idx >> 16;
    int qk = idx & 65535;
    btb[idx] = __float2bfloat16(rpb[rpi[qk]*NHc + h]);
}

// ---------------- LayerNorm: warp per token ----------------------------------
__global__ __launch_bounds__(256) void ln_kernel(
        const float* __restrict__ x, const float* __restrict__ g,
        const float* __restrict__ b, bf16* __restrict__ out) {
    int t = (blockIdx.x * 256 + threadIdx.x) >> 5;
    int lane = threadIdx.x & 31;
    const float* row = x + (size_t)t * Cc;
    float v[6], s = 0.f, ss = 0.f;
    #pragma unroll
    for (int i = 0; i < 6; i++) {
        v[i] = row[i*32 + lane];
        s += v[i]; ss += v[i]*v[i];
    }
    #pragma unroll
    for (int o = 16; o; o >>= 1) {
        s  += __shfl_xor_sync(0xffffffffu, s, o);
        ss += __shfl_xor_sync(0xffffffffu, ss, o);
    }
    float m = s * (1.f/Cc);
    float inv = rsqrtf(ss * (1.f/Cc) - m*m + 1e-5f);
    #pragma unroll
    for (int i = 0; i < 6; i++) {
        int c = i*32 + lane;
        out[(size_t)t*Cc + c] = __float2bfloat16((v[i] - m)*inv*g[c] + b[c]);
    }
}

// ---------------- MMA compute for one 128x64x32 chunk ------------------------
__device__ __forceinline__ void mma_chunk(const bf16* As, const bf16* Bs,
        int wm, int wn, int lane, float acc[2][4][4]) {
    #pragma unroll
    for (int kk = 0; kk < 32; kk += 16) {
        uint32_t af[2][4], bq[2][4];
        #pragma unroll
        for (int mi = 0; mi < 2; mi++) {
            int r = wm*32 + mi*16 + (lane & 15);
            int kofs = kk + ((lane >> 4) << 3);
            ldsm4(af[mi], (uint32_t)__cvta_generic_to_shared(As + r*AP + kofs));
        }
        #pragma unroll
        for (int nh = 0; nh < 2; nh++) {
            int krow = kk + (lane & 7) + (lane & 8);
            int ncol = wn*32 + nh*16 + ((lane >> 4) << 3);
            ldsm4t(bq[nh], (uint32_t)__cvta_generic_to_shared(Bs + krow*BP2 + ncol));
        }
        #pragma unroll
        for (int mi = 0; mi < 2; mi++) {
            mma_bf16(acc[mi][0], af[mi], &bq[0][0]);
            mma_bf16(acc[mi][1], af[mi], &bq[0][2]);
            mma_bf16(acc[mi][2], af[mi], &bq[1][0]);
            mma_bf16(acc[mi][3], af[mi], &bq[1][2]);
        }
    }
}

// ---------------- GEMM: MODE 0 bf16; 1 gelu bf16; 2 fp32+res; 3 proj-combine -
// 3-stage cp.async pipeline, one __syncthreads per chunk.
template<int MODE, int GATHER>
__global__ __launch_bounds__(256, 2) void mma_gemm(
        const bf16* __restrict__ A, const bf16* __restrict__ W,
        const float* __restrict__ bias, void* __restrict__ Cout_,
        const float* __restrict__ Rres, const float* __restrict__ xres,
        const bf16* __restrict__ cv2b, const float* __restrict__ cab,
        int K, int N) {
    __shared__ __align__(16) bf16 As[3][128*AP];
    __shared__ __align__(16) bf16 Bs[3][32*BP2];
    int tid = threadIdx.x;
    int m0 = blockIdx.x * 128, n0 = blockIdx.y * 64;
    int warp = tid >> 5, lane = tid & 31;
    int wm = warp & 3, wn = warp >> 2;
    int g = lane >> 2, tg = lane & 3;
    int nk = K >> 5;

    auto loadA = [&](bf16* dst, int k0) {
        #pragma unroll
        for (int i = 0; i < 2; i++) {
            int idx = tid + i*256;
            int r = idx >> 2, kc = idx & 3;
            const bf16* src;
            if (GATHER) {
                int t = m0 + r; int n = t & 255, win = t >> 8;
                int b = win >> 6, wl = win & 63;
                int hh = (((wl >> 3) << 4) + (n >> 4) + SSc) & 127;
                int ww = (((wl & 7) << 4) + (n & 15) + SSc) & 127;
                src = A + ((size_t)((b*Hc + hh)*Wc + ww))*K + k0 + kc*8;
            } else {
                src = A + (size_t)(m0 + r)*K + k0 + kc*8;
            }
            CP16((uint32_t)__cvta_generic_to_shared(dst + r*AP + kc*8), src);
        }
    };
    auto loadB = [&](bf16* dst, int k0) {
        int k = tid >> 3, nc = tid & 7;
        CP16((uint32_t)__cvta_generic_to_shared(dst + k*BP2 + nc*8),
             W + (size_t)(k0 + k)*N + n0 + nc*8);
    };

    float acc[2][4][4];
    #pragma unroll
    for (int a = 0; a < 2; a++)
        #pragma unroll
        for (int b = 0; b < 4; b++)
            #pragma unroll
            for (int c = 0; c < 4; c++) acc[a][b][c] = 0.f;

    loadA(As[0], 0); loadB(Bs[0], 0); CP_COMMIT;
    if (nk > 1) { loadA(As[1], 32); loadB(Bs[1], 32); }
    CP_COMMIT;

    int sl = 0;
    for (int c = 0; c < nk; c++) {
        CP_WAITG1;
        __syncthreads();
        mma_chunk(As[sl], Bs[sl], wm, wn, lane, acc);
        int nx = c + 2;
        int sn = sl + 2; if (sn >= 3) sn -= 3;
        if (nx < nk) { loadA(As[sn], nx*32); loadB(Bs[sn], nx*32); }
        CP_COMMIT;
        if (++sl == 3) sl = 0;
    }

    #pragma unroll
    for (int mi = 0; mi < 2; mi++) {
        #pragma unroll
        for (int nj = 0; nj < 4; nj++) {
            int r1 = m0 + wm*32 + mi*16 + g;
            int r2 = r1 + 8;
            int cg = n0 + wn*32 + nj*8 + tg*2;
            float b0 = bias[cg], b1 = bias[cg+1];
            float v00 = acc[mi][nj][0] + b0, v01 = acc[mi][nj][1] + b1;
            float v10 = acc[mi][nj][2] + b0, v11 = acc[mi][nj][3] + b1;
            if (MODE == 0) {
                bf16* C = (bf16*)Cout_;
                *(__nv_bfloat162*)(C + (size_t)r1*N + cg) = __floats2bfloat162_rn(v00, v01);
                *(__nv_bfloat162*)(C + (size_t)r2*N + cg) = __floats2bfloat162_rn(v10, v11);
            } else if (MODE == 1) {
                bf16* C = (bf16*)Cout_;
                *(__nv_bfloat162*)(C + (size_t)r1*N + cg) =
                    __floats2bfloat162_rn(gelu_exact(v00), gelu_exact(v01));
                *(__nv_bfloat162*)(C + (size_t)r2*N + cg) =
                    __floats2bfloat162_rn(gelu_exact(v10), gelu_exact(v11));
            } else if (MODE == 2) {
                float* C = (float*)Cout_;
                float2 ra = *(const float2*)(Rres + (size_t)r1*N + cg);
                float2 rb = *(const float2*)(Rres + (size_t)r2*N + cg);
                *(float2*)(C + (size_t)r1*N + cg) = make_float2(v00+ra.x, v01+ra.y);
                *(float2*)(C + (size_t)r2*N + cg) = make_float2(v10+rb.x, v11+rb.y);
            } else {
                float* Y = (float*)Cout_;
                int rr[2] = {r1, r2};
                float vv[2][2] = {{v00, v01}, {v10, v11}};
                #pragma unroll
                for (int q = 0; q < 2; q++) {
                    int t = rr[q];
                    int n = t & 255, win = t >> 8;
                    int b = win >> 6, wl = win & 63;
                    int hh = ((wl >> 3) << 4) + (n >> 4);
                    int ww = ((wl & 7) << 4) + (n & 15);
                    int oh = (hh + SSc) & 127, ow = (ww + SSc) & 127;
                    size_t p = (size_t)((b*Hc + oh)*Wc + ow);
                    float2 xv = *(const float2*)(xres + p*Cc + cg);
                    float2 cav = *(const float2*)(cab + b*Cc + cg);
                    float2 cvv = __bfloat1622float2(*(const __nv_bfloat162*)(cv2b + p*Cc + cg));
                    *(float2*)(Y + p*Cc + cg) = make_float2(
                        xv.x + vv[q][0] + cvv.x*cav.x*0.01f,
                        xv.y + vv[q][1] + cvv.y*cav.y*0.01f);
                }
            }
        }
    }
}

// ---------------- 3x3 conv (implicit GEMM, 3-stage pipeline) ------------------
template<int MODE>
__global__ __launch_bounds__(256, 2) void mma_conv(
        const bf16* __restrict__ X, const bf16* __restrict__ Wt,
        const float* __restrict__ bias, bf16* __restrict__ Y,
        int Cin, int Cout) {
    __shared__ __align__(16) bf16 As[3][128*AP];
    __shared__ __align__(16) bf16 Bs[3][32*BP2];
    int bi = blockIdx.x;
    int b = bi >> 7, h = bi & 127;
    int n0 = blockIdx.y * 64;
    int tid = threadIdx.x;
    int warp = tid >> 5, lane = tid & 31;
    int wm = warp & 3, wn = warp >> 2;
    int g = lane >> 2, tg = lane & 3;
    int ck = Cin >> 5;
    int nk = 9 * ck;

    auto loadA = [&](bf16* dst, int chunk) {
        int tap = chunk / ck, cc = chunk - tap*ck;
        int ci0 = cc * 32;
        int dh = tap/3 - 1, dw = tap%3 - 1;
        int ih = h + dh;
        bool rowok = (ih >= 0 && ih < Hc);
        int ihc = min(max(ih, 0), Hc-1);
        #pragma unroll
        for (int i = 0; i < 2; i++) {
            int idx = tid + i*256;
            int r = idx >> 2, kc = idx & 3;
            int iw = r + dw;
            int sz = (rowok && iw >= 0 && iw < Wc) ? 16 : 0;
            int iwc = min(max(iw, 0), Wc-1);
            const bf16* src = X + ((size_t)((b*Hc + ihc)*Wc + iwc))*Cin + ci0 + kc*8;
            CP16Z((uint32_t)__cvta_generic_to_shared(dst + r*AP + kc*8), src, sz);
        }
    };
    auto loadB = [&](bf16* dst, int chunk) {
        int tap = chunk / ck, cc = chunk - tap*ck;
        int ci0 = cc * 32;
        int k = tid >> 3, nc = tid & 7;
        CP16((uint32_t)__cvta_generic_to_shared(dst + k*BP2 + nc*8),
             Wt + (size_t)(tap*Cin + ci0 + k)*Cout + n0 + nc*8);
    };

    float acc[2][4][4];
    #pragma unroll
    for (int a = 0; a < 2; a++)
        #pragma unroll
        for (int bb = 0; bb < 4; bb++)
            #pragma unroll
            for (int c = 0; c < 4; c++) acc[a][bb][c] = 0.f;

    loadA(As[0], 0); loadB(Bs[0], 0); CP_COMMIT;
    loadA(As[1], 1); loadB(Bs[1], 1); CP_COMMIT;

    int sl = 0;
    for (int c = 0; c < nk; c++) {
        CP_WAITG1;
        __syncthreads();
        mma_chunk(As[sl], Bs[sl], wm, wn, lane, acc);
        int nx = c + 2;
        int sn = sl + 2; if (sn >= 3) sn -= 3;
        if (nx < nk) { loadA(As[sn], nx); loadB(Bs[sn], nx); }
        CP_COMMIT;
        if (++sl == 3) sl = 0;
    }

    #pragma unroll
    for (int mi = 0; mi < 2; mi++) {
        #pragma unroll
        for (int nj = 0; nj < 4; nj++) {
            int p1 = (b*Hc + h)*Wc + wm*32 + mi*16 + g;
            int p2 = p1 + 8;
            int cg = n0 + wn*32 + nj*8 + tg*2;
            float b0 = bias[cg], b1 = bias[cg+1];
            float v00 = acc[mi][nj][0] + b0, v01 = acc[mi][nj][1] + b1;
            float v10 = acc[mi][nj][2] + b0, v11 = acc[mi][nj][3] + b1;
            if (MODE == 1) {
                v00 = gelu_exact(v00); v01 = gelu_exact(v01);
                v10 = gelu_exact(v10); v11 = gelu_exact(v11);
            }
            *(__nv_bfloat162*)(Y + (size_t)p1*Cout + cg) = __floats2bfloat162_rn(v00, v01);
            *(__nv_bfloat162*)(Y + (size_t)p2*Cout + cg) = __floats2bfloat162_rn(v10, v11);
        }
    }
}

// ---------------- pool + channel attention -----------------------------------
__global__ void pool_kernel(const bf16* __restrict__ cv2b, float* __restrict__ pp) {
    int blk = blockIdx.x;
    int b = blk >> 6, chunk = blk & 63;
    int c = threadIdx.x;
    float s = 0.f;
    int base = b*16384 + chunk*256;
    for (int p = 0; p < 256; p++) s += __bfloat162float(cv2b[(size_t)(base + p)*Cc + c]);
    pp[blk*Cc + c] = s;
}

__global__ void ca_kernel(const float* __restrict__ pp,
                          const float* __restrict__ w1, const float* __restrict__ b1,
                          const float* __restrict__ w2, const float* __restrict__ b2,
                          float* __restrict__ ca) {
    __shared__ float pooled[Bc*Cc];
    __shared__ float t1[Bc*6];
    int tid = threadIdx.x;
    for (int i = tid; i < Bc*Cc; i += 256) {
        int b = i / Cc, c = i % Cc;
        float s = 0.f;
        for (int j = 0; j < 64; j++) s += pp[(b*64 + j)*Cc + c];
        pooled[i] = s * (1.f/16384.f);
    }
    __syncthreads();
    if (tid < Bc*6) {
        int b = tid / 6, j = tid % 6;
        float s = b1[j];
        for (int c = 0; c < Cc; c++) s += pooled[b*Cc + c] * w1[c*6 + j];
        t1[tid] = fmaxf(s, 0.f);
    }
    __syncthreads();
    for (int i = tid; i < Bc*Cc; i += 256) {
        int b = i / Cc, c = i % Cc;
        float s = b2[c];
        #pragma unroll
        for (int j = 0; j < 6; j++) s += t1[b*6 + j] * w2[j*Cc + c];
        ca[i] = 1.f / (1.f + expf(-s));
    }
}

// ---------------- flash window attention via tensor-core MMA ------------------
// Bias from per-head L2-resident table; shift-mask computed inline from coords.
__global__ __launch_bounds__(256) void attn_mma(
        const bf16* __restrict__ qkvb, const bf16* __restrict__ btb,
        bf16* __restrict__ out) {
    extern __shared__ __align__(16) bf16 smA[];
    bf16* Qs = smA;
    bf16* Ks = smA + 256*QP;
    bf16* Vs = smA + 2*256*QP;
    int win = blockIdx.x, h = blockIdx.y;
    int tid = threadIdx.x;
    int warp = tid >> 5, lane = tid & 31;
    int g = lane >> 2, tg = lane & 3;
    int m0 = warp * 32;

    {
        const uint4* src = (const uint4*)(qkvb + (size_t)(win*Nc + tid)*576 + h*HDc);
        uint4* qd = (uint4*)(Qs + tid*QP);
        uint4* kd = (uint4*)(Ks + tid*QP);
        uint4* vd = (uint4*)(Vs + tid*QP);
        #pragma unroll
        for (int i = 0; i < 4; i++) {
            qd[i] = src[i];
            kd[i] = src[i + 24];
            vd[i] = src[i + 48];
        }
    }
    __syncthreads();

    uint32_t qf[2][2][4];
    #pragma unroll
    for (int mi = 0; mi < 2; mi++)
        #pragma unroll
        for (int ks = 0; ks < 2; ks++) {
            int r = m0 + mi*16 + (lane & 15);
            int kofs = ks*16 + ((lane >> 4) << 3);
            ldsm4(qf[mi][ks], (uint32_t)__cvta_generic_to_shared(Qs + r*QP + kofs));
        }

    const bf16* cb = btb + ((size_t)h << 16);

    // shift-mask labels
    int wl = win & 63;
    bool er = (wl >> 3) == 7, ec = (wl & 7) == 7;
    bool edge = er || ec;
    int lq[2][2];
    #pragma unroll
    for (int mi = 0; mi < 2; mi++)
        #pragma unroll
        for (int rh = 0; rh < 2; rh++) {
            int q = m0 + mi*16 + g + rh*8;
            int rc = er ? (((q >> 4) < 8) ? 1 : 2) : 0;
            int cc = ec ? (((q & 15) < 8) ? 1 : 2) : 0;
            lq[mi][rh] = rc*3 + cc;
        }

    float mx[2][2], lsum[2][2];
    float o[2][4][4];
    #pragma unroll
    for (int mi = 0; mi < 2; mi++)
        #pragma unroll
        for (int rh = 0; rh < 2; rh++) { mx[mi][rh] = -1e30f; lsum[mi][rh] = 0.f; }
    #pragma unroll
    for (int mi = 0; mi < 2; mi++)
        #pragma unroll
        for (int nt = 0; nt < 4; nt++)
            #pragma unroll
            for (int e = 0; e < 4; e++) o[mi][nt][e] = 0.f;

    for (int c0 = 0; c0 < Nc; c0 += 32) {
        float s[2][4][4];
        #pragma unroll
        for (int mi = 0; mi < 2; mi++)
            #pragma unroll
            for (int nj = 0; nj < 4; nj++)
                #pragma unroll
                for (int e = 0; e < 4; e++) s[mi][nj][e] = 0.f;

        // ---- S = Q K^T
        #pragma unroll
        for (int ks = 0; ks < 2; ks++) {
            uint32_t kf[2][4];
            #pragma unroll
            for (int np = 0; np < 2; np++) {
                int n = c0 + np*16 + (lane & 7) + ((lane >> 4) << 3);
                int kc = ks*16 + ((lane >> 3) & 1)*8;
                ldsm4(kf[np], (uint32_t)__cvta_generic_to_shared(Ks + n*QP + kc));
            }
            #pragma unroll
            for (int mi = 0; mi < 2; mi++) {
                mma_bf16(s[mi][0], qf[mi][ks], &kf[0][0]);
                mma_bf16(s[mi][1], qf[mi][ks], &kf[0][2]);
                mma_bf16(s[mi][2], qf[mi][ks], &kf[1][0]);
                mma_bf16(s[mi][3], qf[mi][ks], &kf[1][2]);
            }
        }

        // ---- scale + bias (+ inline shift mask) + online softmax
        int lk[4][2];
        if (edge) {
            #pragma unroll
            for (int nj = 0; nj < 4; nj++)
                #pragma unroll
                for (int e = 0; e < 2; e++) {
                    int kcol = c0 + nj*8 + tg*2 + e;
                    int rc = er ? (((kcol >> 4) < 8) ? 1 : 2) : 0;
                    int cc = ec ? (((kcol & 15) < 8) ? 1 : 2) : 0;
                    lk[nj][e] = rc*3 + cc;
                }
        }
        #pragma unroll
        for (int mi = 0; mi < 2; mi++) {
            int row0 = m0 + mi*16 + g;
            #pragma unroll
            for (int nj = 0; nj < 4; nj++) {
                int col = c0 + nj*8 + tg*2;
                float2 b0 = __bfloat1622float2(*(const __nv_bfloat162*)(cb + (size_t)row0*Nc + col));
                float2 b1 = __bfloat1622float2(*(const __nv_bfloat162*)(cb + (size_t)(row0+8)*Nc + col));
                s[mi][nj][0] = s[mi][nj][0]*ATT_SCALE + b0.x;
                s[mi][nj][1] = s[mi][nj][1]*ATT_SCALE + b0.y;
                s[mi][nj][2] = s[mi][nj][2]*ATT_SCALE + b1.x;
                s[mi][nj][3] = s[mi][nj][3]*ATT_SCALE + b1.y;
                if (edge) {
                    s[mi][nj][0] += (lq[mi][0] == lk[nj][0]) ? 0.f : -100.f;
                    s[mi][nj][1] += (lq[mi][0] == lk[nj][1]) ? 0.f : -100.f;
                    s[mi][nj][2] += (lq[mi][1] == lk[nj][0]) ? 0.f : -100.f;
                    s[mi][nj][3] += (lq[mi][1] == lk[nj][1]) ? 0.f : -100.f;
                }
            }
            #pragma unroll
            for (int rh = 0; rh < 2; rh++) {
                int e0 = rh*2;
                float m_ = fmaxf(fmaxf(s[mi][0][e0], s[mi][0][e0+1]),
                                 fmaxf(s[mi][1][e0], s[mi][1][e0+1]));
                m_ = fmaxf(m_, fmaxf(fmaxf(s[mi][2][e0], s[mi][2][e0+1]),
                                     fmaxf(s[mi][3][e0], s[mi][3][e0+1])));
                m_ = fmaxf(m_, __shfl_xor_sync(0xffffffffu, m_, 1));
                m_ = fmaxf(m_, __shfl_xor_sync(0xffffffffu, m_, 2));
                float newm = fmaxf(mx[mi][rh], m_);
                float sc = __expf(mx[mi][rh] - newm);
                mx[mi][rh] = newm;
                float ps = 0.f;
                #pragma unroll
                for (int nj = 0; nj < 4; nj++) {
                    float p0 = __expf(s[mi][nj][e0]   - newm);
                    float p1 = __expf(s[mi][nj][e0+1] - newm);
                    s[mi][nj][e0] = p0; s[mi][nj][e0+1] = p1;
                    ps += p0 + p1;
                }
                ps += __shfl_xor_sync(0xffffffffu, ps, 1);
                ps += __shfl_xor_sync(0xffffffffu, ps, 2);
                lsum[mi][rh] = lsum[mi][rh]*sc + ps;
                #pragma unroll
                for (int nt = 0; nt < 4; nt++) {
                    o[mi][nt][e0]   *= sc;
                    o[mi][nt][e0+1] *= sc;
                }
            }
        }

        // ---- O += P V
        #pragma unroll
        for (int ks2 = 0; ks2 < 2; ks2++) {
            uint32_t vf[2][4];
            int krow = c0 + ks2*16 + (lane & 7) + (lane & 8);
            #pragma unroll
            for (int dp = 0; dp < 2; dp++)
                ldsm4t(vf[dp], (uint32_t)__cvta_generic_to_shared(
                    Vs + krow*QP + dp*16 + ((lane >> 4) << 3)));
            #pragma unroll
            for (int mi = 0; mi < 2; mi++) {
                uint32_t af[4];
                af[0] = pkbf2(s[mi][2*ks2][0],   s[mi][2*ks2][1]);
                af[1] = pkbf2(s[mi][2*ks2][2],   s[mi][2*ks2][3]);
                af[2] = pkbf2(s[mi][2*ks2+1][0], s[mi][2*ks2+1][1]);
                af[3] = pkbf2(s[mi][2*ks2+1][2], s[mi][2*ks2+1][3]);
                mma_bf16(o[mi][0], af, &vf[0][0]);
                mma_bf16(o[mi][1], af, &vf[0][2]);
                mma_bf16(o[mi][2], af, &vf[1][0]);
                mma_bf16(o[mi][3], af, &vf[1][2]);
            }
        }
    }

    #pragma unroll
    for (int mi = 0; mi < 2; mi++) {
        #pragma unroll
        for (int rh = 0; rh < 2; rh++) {
            float inv = 1.f / lsum[mi][rh];
            int row = win*Nc + m0 + mi*16 + g + rh*8;
            bf16* orow = out + (size_t)row*Cc + h*HDc;
            #pragma unroll
            for (int nt = 0; nt < 4; nt++) {
                *(__nv_bfloat162*)(orow + nt*8 + tg*2) =
                    __floats2bfloat162_rn(o[mi][nt][rh*2]*inv, o[mi][nt][rh*2+1]*inv);
            }
        }
    }
}

// ---------------- launch -----------------------------------------------------
extern "C" void kernel_launch(void* const* d_in, const int* in_sizes, int n_in,
                              void* d_out, int out_size) {
    const float* x     = (const float*)d_in[0];
    const float* qkv_w = (const float*)d_in[1];
    const float* qkv_b = (const float*)d_in[2];
    const float* proj_w= (const float*)d_in[3];
    const float* proj_b= (const float*)d_in[4];
    const float* rpb   = (const float*)d_in[5];
    const float* n1w   = (const float*)d_in[6];
    const float* n1b   = (const float*)d_in[7];
    const float* n2w   = (const float*)d_in[8];
    const float* n2b   = (const float*)d_in[9];
    const float* c1w   = (const float*)d_in[10];
    const float* c1b   = (const float*)d_in[11];
    const float* c2w   = (const float*)d_in[12];
    const float* c2b   = (const float*)d_in[13];
    const float* ca1w  = (const float*)d_in[14];
    const float* ca1b  = (const float*)d_in[15];
    const float* ca2w  = (const float*)d_in[16];
    const float* ca2b  = (const float*)d_in[17];
    const float* fc1w  = (const float*)d_in[18];
    const float* fc1b  = (const float*)d_in[19];
    const float* fc2w  = (const float*)d_in[20];
    const float* fc2b  = (const float*)d_in[21];
    const int*   rpi   = (const int*)d_in[22];
    float* out = (float*)d_out;

    bf16 *xnb, *qkvb, *atb, *cv1b, *cv2b, *ynb, *hb, *btb;
    bf16 *wqkv, *wproj, *wfc1, *wfc2, *wc1, *wc2;
    float *y, *pp, *cab;
    cudaGetSymbolAddress((void**)&xnb,  g_xnb);
    cudaGetSymbolAddress((void**)&qkvb, g_qkvb);
    cudaGetSymbolAddress((void**)&atb,  g_atb);
    cudaGetSymbolAddress((void**)&cv1b, g_cv1b);
    cudaGetSymbolAddress((void**)&cv2b, g_cv2b);
    cudaGetSymbolAddress((void**)&y,    g_y);
    cudaGetSymbolAddress((void**)&ynb,  g_ynb);
    cudaGetSymbolAddress((void**)&hb,   g_hb);
    cudaGetSymbolAddress((void**)&pp,   g_pp);
    cudaGetSymbolAddress((void**)&cab,  g_ca);
    cudaGetSymbolAddress((void**)&btb,  g_btb);
    cudaGetSymbolAddress((void**)&wqkv, g_wqkv);
    cudaGetSymbolAddress((void**)&wproj,g_wproj);
    cudaGetSymbolAddress((void**)&wfc1, g_wfc1);
    cudaGetSymbolAddress((void**)&wfc2, g_wfc2);
    cudaGetSymbolAddress((void**)&wc1,  g_wc1);
    cudaGetSymbolAddress((void**)&wc2,  g_wc2);

    static bool attr_set = false;
    if (!attr_set) {
        cudaFuncSetAttribute(attn_mma, cudaFuncAttributeMaxDynamicSharedMemorySize,
                             3*256*QP*sizeof(bf16));
        attr_set = true;
    }

    // weight converts (single launch) + per-head bias table
    f2b_all<<<(STOT + 255)/256, 256>>>(qkv_w, proj_w, fc1w, fc2w, c1w, c2w,
                                       wqkv, wproj, wfc1, wfc2, wc1, wc2);
    btb_kernel<<<NHc*Nc*Nc/256, 256>>>(rpb, rpi, btb);

    // LN1
    ln_kernel<<<NPIX/8, 256>>>(x, n1w, n1b, xnb);
    // conv branch
    mma_conv<1><<<dim3(Bc*Hc, 1), 256>>>(xnb, wc1, c1b, cv1b, Cc, 64);
    mma_conv<0><<<dim3(Bc*Hc, 3), 256>>>(cv1b, wc2, c2b, cv2b, 64, Cc);
    pool_kernel<<<Bc*64, Cc>>>(cv2b, pp);
    ca_kernel<<<1, 256>>>(pp, ca1w, ca1b, ca2w, ca2b, cab);
    // attention branch (gather fused into qkv A-load)
    mma_gemm<0, 1><<<dim3(NPIX/128, 9), 256>>>(xnb, wqkv, qkv_b, qkvb,
                                               nullptr, nullptr, nullptr, nullptr, Cc, 3*Cc);
    attn_mma<<<dim3(256, NHc), 256, 3*256*QP*sizeof(bf16)>>>(qkvb, btb, atb);
    // proj + window-reverse + residual combine fused
    mma_gemm<3, 0><<<dim3(NPIX/128, 3), 256>>>(atb, wproj, proj_b, y,
                                               nullptr, x, cv2b, cab, Cc, Cc);
    // MLP
    ln_kernel<<<NPIX/8, 256>>>(y, n2w, n2b, ynb);
    mma_gemm<1, 0><<<dim3(NPIX/128, 12), 256>>>(ynb, wfc1, fc1b, hb,
                                                nullptr, nullptr, nullptr, nullptr, Cc, 4*Cc);
    mma_gemm<2, 0><<<dim3(NPIX/128, 3), 256>>>(hb, wfc2, fc2b, out,
                                               y, nullptr, nullptr, nullptr, 4*Cc, Cc);
}

// round 10
// speedup vs baseline: 7.5642x; 1.0961x over previous
#include <cuda_runtime.h>
#include <cuda_bf16.h>
#include <math.h>
#include <stdint.h>

typedef __nv_bfloat16 bf16;

#define Bc 4
#define Hc 128
#define Wc 128
#define Cc 192
#define NHc 6
#define WSc 16
#define SSc 8
#define Nc 256
#define HDc 32
#define NPIX (Bc*Hc*Wc)            // 65536
#define ATT_SCALE 0.17677669529663687f

#define AP 40       // A smem row stride (bf16 elems)
#define BP2 72      // B smem row stride
#define QP 40       // attention smem row stride

// ---------------- scratch (device globals) -----------------------------------
__device__ bf16  g_xnb [NPIX*Cc];
__device__ bf16  g_qkvb[(size_t)NPIX*3*Cc];
__device__ bf16  g_atb [NPIX*Cc];
__device__ bf16  g_cv1b[NPIX*64];
__device__ bf16  g_cv2b[NPIX*Cc];
__device__ float g_y   [NPIX*Cc];
__device__ bf16  g_ynb [NPIX*Cc];
__device__ bf16  g_hb  [(size_t)NPIX*4*Cc];
__device__ float g_pp  [Bc*64*Cc];
__device__ float g_ca  [Bc*Cc];
__device__ bf16  g_btb [NHc*Nc*Nc];
__device__ bf16  g_wqkv [Cc*3*Cc];
__device__ bf16  g_wproj[Cc*Cc];
__device__ bf16  g_wfc1 [Cc*4*Cc];
__device__ bf16  g_wfc2 [4*Cc*Cc];
__device__ bf16  g_wc1  [9*Cc*64];
__device__ bf16  g_wc2  [9*64*Cc];

__device__ __forceinline__ float gelu_exact(float x) {
    return 0.5f * x * (1.f + erff(x * 0.70710678118654752f));
}

// ---------------- ptx helpers ------------------------------------------------
#define CP16(dst, src) asm volatile("cp.async.cg.shared.global [%0], [%1], 16;\n" :: "r"(dst), "l"(src))
#define CP16Z(dst, src, sz) asm volatile("cp.async.cg.shared.global [%0], [%1], 16, %2;\n" :: "r"(dst), "l"(src), "r"(sz))
#define CP_COMMIT asm volatile("cp.async.commit_group;\n")
#define CP_WAITG1 asm volatile("cp.async.wait_group 1;\n")

__device__ __forceinline__ void ldsm4(uint32_t* r, uint32_t a) {
    asm volatile("ldmatrix.sync.aligned.m8n8.x4.shared.b16 {%0,%1,%2,%3},[%4];"
        : "=r"(r[0]), "=r"(r[1]), "=r"(r[2]), "=r"(r[3]) : "r"(a));
}
__device__ __forceinline__ void ldsm4t(uint32_t* r, uint32_t a) {
    asm volatile("ldmatrix.sync.aligned.m8n8.x4.trans.shared.b16 {%0,%1,%2,%3},[%4];"
        : "=r"(r[0]), "=r"(r[1]), "=r"(r[2]), "=r"(r[3]) : "r"(a));
}
__device__ __forceinline__ void mma_bf16(float* c, const uint32_t* a, const uint32_t* b) {
    asm volatile(
        "mma.sync.aligned.m16n8k16.row.col.f32.bf16.bf16.f32 "
        "{%0,%1,%2,%3}, {%4,%5,%6,%7}, {%8,%9}, {%0,%1,%2,%3};\n"
        : "+f"(c[0]), "+f"(c[1]), "+f"(c[2]), "+f"(c[3])
        : "r"(a[0]), "r"(a[1]), "r"(a[2]), "r"(a[3]), "r"(b[0]), "r"(b[1]));
}
__device__ __forceinline__ uint32_t pkbf2(float a, float b) {
    __nv_bfloat162 t = __floats2bfloat162_rn(a, b);
    return *(uint32_t*)&t;
}

// ---------------- batched weight convert --------------------------------------
#define S0 110592
#define S1 36864
#define S2 147456
#define S3 147456
#define S4 110592
#define S5 110592
#define STOT (S0+S1+S2+S3+S4+S5)
__global__ void f2b_all(const float* __restrict__ a0, const float* __restrict__ a1,
                        const float* __restrict__ a2, const float* __restrict__ a3,
                        const float* __restrict__ a4, const float* __restrict__ a5,
                        bf16* o0, bf16* o1, bf16* o2, bf16* o3, bf16* o4, bf16* o5) {
    int i = blockIdx.x * 256 + threadIdx.x;
    if (i >= STOT) return;
    if (i < S0)                { o0[i] = __float2bfloat16(a0[i]); return; }
    i -= S0;
    if (i < S1)                { o1[i] = __float2bfloat16(a1[i]); return; }
    i -= S1;
    if (i < S2)                { o2[i] = __float2bfloat16(a2[i]); return; }
    i -= S2;
    if (i < S3)                { o3[i] = __float2bfloat16(a3[i]); return; }
    i -= S3;
    if (i < S4)                { o4[i] = __float2bfloat16(a4[i]); return; }
    i -= S4;
    o5[i] = __float2bfloat16(a5[i]);
}

__global__ void btb_kernel(const float* __restrict__ rpb, const int* __restrict__ rpi,
                           bf16* __restrict__ btb) {
    int idx = blockIdx.x * 256 + threadIdx.x;
    int h = idx >> 16;
    int qk = idx & 65535;
    btb[idx] = __float2bfloat16(rpb[rpi[qk]*NHc + h]);
}

// ---------------- LayerNorm: warp per token ----------------------------------
__global__ __launch_bounds__(256) void ln_kernel(
        const float* __restrict__ x, const float* __restrict__ g,
        const float* __restrict__ b, bf16* __restrict__ out) {
    int t = (blockIdx.x * 256 + threadIdx.x) >> 5;
    int lane = threadIdx.x & 31;
    const float* row = x + (size_t)t * Cc;
    float v[6], s = 0.f, ss = 0.f;
    #pragma unroll
    for (int i = 0; i < 6; i++) {
        v[i] = row[i*32 + lane];
        s += v[i]; ss += v[i]*v[i];
    }
    #pragma unroll
    for (int o = 16; o; o >>= 1) {
        s  += __shfl_xor_sync(0xffffffffu, s, o);
        ss += __shfl_xor_sync(0xffffffffu, ss, o);
    }
    float m = s * (1.f/Cc);
    float inv = rsqrtf(ss * (1.f/Cc) - m*m + 1e-5f);
    #pragma unroll
    for (int i = 0; i < 6; i++) {
        int c = i*32 + lane;
        out[(size_t)t*Cc + c] = __float2bfloat16((v[i] - m)*inv*g[c] + b[c]);
    }
}

// ---------------- MMA compute on one staged chunk (precomputed offsets) ------
__device__ __forceinline__ void mma_stage(uint32_t ab, uint32_t bb,
        const uint32_t aoff[2][2], const uint32_t boff[2][2], float acc[2][4][4]) {
    #pragma unroll
    for (int kk = 0; kk < 2; kk++) {
        uint32_t af[2][4], bq[2][4];
        ldsm4(af[0], ab + aoff[0][kk]);
        ldsm4(af[1], ab + aoff[1][kk]);
        ldsm4t(bq[0], bb + boff[kk][0]);
        ldsm4t(bq[1], bb + boff[kk][1]);
        #pragma unroll
        for (int mi = 0; mi < 2; mi++) {
            mma_bf16(acc[mi][0], af[mi], &bq[0][0]);
            mma_bf16(acc[mi][1], af[mi], &bq[0][2]);
            mma_bf16(acc[mi][2], af[mi], &bq[1][0]);
            mma_bf16(acc[mi][3], af[mi], &bq[1][2]);
        }
    }
}

// precompute ldsm byte-offsets (relative to stage base)
__device__ __forceinline__ void mk_mma_offs(int wm, int wn, int lane,
        uint32_t aoff[2][2], uint32_t boff[2][2]) {
    #pragma unroll
    for (int mi = 0; mi < 2; mi++)
        #pragma unroll
        for (int kk = 0; kk < 2; kk++) {
            int r = wm*32 + mi*16 + (lane & 15);
            int ko = kk*16 + ((lane >> 4) << 3);
            aoff[mi][kk] = (uint32_t)((r*AP + ko) * 2);
        }
    #pragma unroll
    for (int kk = 0; kk < 2; kk++)
        #pragma unroll
        for (int nh = 0; nh < 2; nh++) {
            int krow = kk*16 + (lane & 7) + (lane & 8);
            int ncol = wn*32 + nh*16 + ((lane >> 4) << 3);
            boff[kk][nh] = (uint32_t)((krow*BP2 + ncol) * 2);
        }
}

// ---------------- GEMM: MODE 0 bf16; 1 gelu bf16; 2 fp32+res; 3 proj-combine -
template<int MODE, int GATHER, int K, int N>
__global__ __launch_bounds__(256, 2) void mma_gemm(
        const bf16* __restrict__ A, const bf16* __restrict__ W,
        const float* __restrict__ bias, void* __restrict__ Cout_,
        const float* __restrict__ Rres, const float* __restrict__ xres,
        const bf16* __restrict__ cv2b, const float* __restrict__ cab) {
    __shared__ __align__(16) bf16 As[3][128*AP];
    __shared__ __align__(16) bf16 Bs[3][32*BP2];
    constexpr int nk = K >> 5;
    constexpr uint32_t AS_ST = 128*AP*2;
    constexpr uint32_t BS_ST = 32*BP2*2;
    int tid = threadIdx.x;
    int m0 = blockIdx.x * 128, n0 = blockIdx.y * 64;
    int warp = tid >> 5, lane = tid & 31;
    int wm = warp & 3, wn = warp >> 2;
    int g = lane >> 2, tg = lane & 3;

    // hoisted A-load addressing: rows rb, rb+64 ; chunk-local col group kc*8 (0..24)
    int rb = tid >> 2, kc = tid & 3;
    const bf16* srcA[2];
    uint32_t dofA[2];
    #pragma unroll
    for (int i = 0; i < 2; i++) {
        int r = rb + i*64;
        int row;
        if (GATHER) {
            int t = m0 + r; int n = t & 255, win = t >> 8;
            int b = win >> 6, wl = win & 63;
            int hh = (((wl >> 3) << 4) + (n >> 4) + SSc) & 127;
            int ww = (((wl & 7) << 4) + (n & 15) + SSc) & 127;
            row = (b*Hc + hh)*Wc + ww;
        } else row = m0 + r;
        srcA[i] = A + (size_t)row*K + kc*8;
        dofA[i] = (uint32_t)((r*AP + kc*8) * 2);
    }
    // B-load: 32 k-rows x 8 col-groups, 1 load per thread
    int rbB = tid >> 3, kcB = tid & 7;
    const bf16* srcB = W + (size_t)rbB*N + n0 + kcB*8;
    uint32_t dofB = (uint32_t)((rbB*BP2 + kcB*8) * 2);

    uint32_t asb = (uint32_t)__cvta_generic_to_shared(&As[0][0]);
    uint32_t bsb = (uint32_t)__cvta_generic_to_shared(&Bs[0][0]);
    uint32_t aoff[2][2], boff[2][2];
    mk_mma_offs(wm, wn, lane, aoff, boff);

    float acc[2][4][4];
    #pragma unroll
    for (int a = 0; a < 2; a++)
        #pragma unroll
        for (int b = 0; b < 4; b++)
            #pragma unroll
            for (int c = 0; c < 4; c++) acc[a][b][c] = 0.f;

    auto loadAB = [&](int st, int k0) {
        uint32_t ab = asb + st*AS_ST, bb = bsb + st*BS_ST;
        CP16(ab + dofA[0], srcA[0] + k0);
        CP16(ab + dofA[1], srcA[1] + k0);
        CP16(bb + dofB, srcB + (size_t)k0*N);
    };

    loadAB(0, 0); CP_COMMIT;
    if (nk > 1) loadAB(1, 32);
    CP_COMMIT;

    int sl = 0;
    for (int c = 0; c < nk; c++) {
        CP_WAITG1;
        __syncthreads();
        int nx = c + 2;
        int sn = sl + 2; if (sn >= 3) sn -= 3;
        if (nx < nk) loadAB(sn, nx*32);
        CP_COMMIT;
        mma_stage(asb + sl*AS_ST, bsb + sl*BS_ST, aoff, boff, acc);
        if (++sl == 3) sl = 0;
    }

    #pragma unroll
    for (int mi = 0; mi < 2; mi++) {
        #pragma unroll
        for (int nj = 0; nj < 4; nj++) {
            int r1 = m0 + wm*32 + mi*16 + g;
            int r2 = r1 + 8;
            int cg = n0 + wn*32 + nj*8 + tg*2;
            float b0 = bias[cg], b1 = bias[cg+1];
            float v00 = acc[mi][nj][0] + b0, v01 = acc[mi][nj][1] + b1;
            float v10 = acc[mi][nj][2] + b0, v11 = acc[mi][nj][3] + b1;
            if (MODE == 0) {
                bf16* C = (bf16*)Cout_;
                *(__nv_bfloat162*)(C + (size_t)r1*N + cg) = __floats2bfloat162_rn(v00, v01);
                *(__nv_bfloat162*)(C + (size_t)r2*N + cg) = __floats2bfloat162_rn(v10, v11);
            } else if (MODE == 1) {
                bf16* C = (bf16*)Cout_;
                *(__nv_bfloat162*)(C + (size_t)r1*N + cg) =
                    __floats2bfloat162_rn(gelu_exact(v00), gelu_exact(v01));
                *(__nv_bfloat162*)(C + (size_t)r2*N + cg) =
                    __floats2bfloat162_rn(gelu_exact(v10), gelu_exact(v11));
            } else if (MODE == 2) {
                float* C = (float*)Cout_;
                float2 ra = *(const float2*)(Rres + (size_t)r1*N + cg);
                float2 rb2 = *(const float2*)(Rres + (size_t)r2*N + cg);
                *(float2*)(C + (size_t)r1*N + cg) = make_float2(v00+ra.x, v01+ra.y);
                *(float2*)(C + (size_t)r2*N + cg) = make_float2(v10+rb2.x, v11+rb2.y);
            } else {
                float* Y = (float*)Cout_;
                int rr[2] = {r1, r2};
                float vv[2][2] = {{v00, v01}, {v10, v11}};
                #pragma unroll
                for (int q = 0; q < 2; q++) {
                    int t = rr[q];
                    int n = t & 255, win = t >> 8;
                    int b = win >> 6, wl = win & 63;
                    int hh = ((wl >> 3) << 4) + (n >> 4);
                    int ww = ((wl & 7) << 4) + (n & 15);
                    int oh = (hh + SSc) & 127, ow = (ww + SSc) & 127;
                    size_t p = (size_t)((b*Hc + oh)*Wc + ow);
                    float2 xv = *(const float2*)(xres + p*Cc + cg);
                    float2 cav = *(const float2*)(cab + b*Cc + cg);
                    float2 cvv = __bfloat1622float2(*(const __nv_bfloat162*)(cv2b + p*Cc + cg));
                    *(float2*)(Y + p*Cc + cg) = make_float2(
                        xv.x + vv[q][0] + cvv.x*cav.x*0.01f,
                        xv.y + vv[q][1] + cvv.y*cav.y*0.01f);
                }
            }
        }
    }
}

// ---------------- 3x3 conv (implicit GEMM, hoisted addressing) ----------------
template<int MODE, int Cin, int Cout>
__global__ __launch_bounds__(256, 2) void mma_conv(
        const bf16* __restrict__ X, const bf16* __restrict__ Wt,
        const float* __restrict__ bias, bf16* __restrict__ Y) {
    __shared__ __align__(16) bf16 As[3][128*AP];
    __shared__ __align__(16) bf16 Bs[3][32*BP2];
    constexpr int CCH = Cin >> 5;
    constexpr int nk = 9 * CCH;
    constexpr uint32_t AS_ST = 128*AP*2;
    constexpr uint32_t BS_ST = 32*BP2*2;
    int bi = blockIdx.x;
    int b = bi >> 7, h = bi & 127;
    int n0 = blockIdx.y * 64;
    int tid = threadIdx.x;
    int warp = tid >> 5, lane = tid & 31;
    int wm = warp & 3, wn = warp >> 2;
    int g = lane >> 2, tg = lane & 3;

    // A-load: 2 rows per thread (rb2, rb2+64), kc4 = chunk-local 8-elem group
    int rb2 = tid >> 2, kc4 = tid & 3;
    uint32_t dofA[2];
    dofA[0] = (uint32_t)((rb2*AP + kc4*8) * 2);
    dofA[1] = (uint32_t)(((rb2+64)*AP + kc4*8) * 2);
    // per-dh row bases (clamped) + ok flags
    const bf16* rowbase[3];
    bool okH[3];
    #pragma unroll
    for (int d = 0; d < 3; d++) {
        int ih = h + d - 1;
        okH[d] = (ih >= 0 && ih < Hc);
        int ihc = min(max(ih, 0), Hc-1);
        rowbase[d] = X + (size_t)((b*Hc + ihc)*Wc) * Cin + kc4*8;
    }
    // per-dw column offsets + ok flags for this thread's 2 rows
    int iwc[3][2]; bool okW[3][2];
    #pragma unroll
    for (int d = 0; d < 3; d++)
        #pragma unroll
        for (int i = 0; i < 2; i++) {
            int r = rb2 + i*64;
            int iw = r + d - 1;
            okW[d][i] = (iw >= 0 && iw < Wc);
            iwc[d][i] = min(max(iw, 0), Wc-1);
        }
    // B: linear in global k = chunk*32 + kb
    const bf16* srcB = Wt + (size_t)(tid >> 3)*Cout + n0 + (tid & 7)*8;
    uint32_t dofB = (uint32_t)(((tid >> 3)*BP2 + (tid & 7)*8) * 2);

    uint32_t asb = (uint32_t)__cvta_generic_to_shared(&As[0][0]);
    uint32_t bsb = (uint32_t)__cvta_generic_to_shared(&Bs[0][0]);
    uint32_t aoff[2][2], boff[2][2];
    mk_mma_offs(wm, wn, lane, aoff, boff);

    float acc[2][4][4];
    #pragma unroll
    for (int a = 0; a < 2; a++)
        #pragma unroll
        for (int bb = 0; bb < 4; bb++)
            #pragma unroll
            for (int c = 0; c < 4; c++) acc[a][bb][c] = 0.f;

    auto loadAB = [&](int st, int chunk) {
        int tap = chunk / CCH;           // compile-time divisor
        int ci0 = (chunk - tap*CCH) * 32;
        int dh = tap/3, dw = tap - dh*3; // 0..2 each
        uint32_t ab = asb + st*AS_ST, bb = bsb + st*BS_ST;
        const bf16* rbp = rowbase[dh] + ci0;
        #pragma unroll
        for (int i = 0; i < 2; i++) {
            int sz = (okH[dh] && okW[dw][i]) ? 16 : 0;
            CP16Z(ab + dofA[i], rbp + (size_t)iwc[dw][i]*Cin, sz);
        }
        CP16(bb + dofB, srcB + (size_t)chunk*32*Cout);
    };

    loadAB(0, 0); CP_COMMIT;
    loadAB(1, 1); CP_COMMIT;

    int sl = 0;
    for (int c = 0; c < nk; c++) {
        CP_WAITG1;
        __syncthreads();
        int nx = c + 2;
        int sn = sl + 2; if (sn >= 3) sn -= 3;
        if (nx < nk) loadAB(sn, nx);
        CP_COMMIT;
        mma_stage(asb + sl*AS_ST, bsb + sl*BS_ST, aoff, boff, acc);
        if (++sl == 3) sl = 0;
    }

    #pragma unroll
    for (int mi = 0; mi < 2; mi++) {
        #pragma unroll
        for (int nj = 0; nj < 4; nj++) {
            int p1 = (b*Hc + h)*Wc + wm*32 + mi*16 + g;
            int p2 = p1 + 8;
            int cg = n0 + wn*32 + nj*8 + tg*2;
            float b0 = bias[cg], b1 = bias[cg+1];
            float v00 = acc[mi][nj][0] + b0, v01 = acc[mi][nj][1] + b1;
            float v10 = acc[mi][nj][2] + b0, v11 = acc[mi][nj][3] + b1;
            if (MODE == 1) {
                v00 = gelu_exact(v00); v01 = gelu_exact(v01);
                v10 = gelu_exact(v10); v11 = gelu_exact(v11);
            }
            *(__nv_bfloat162*)(Y + (size_t)p1*Cout + cg) = __floats2bfloat162_rn(v00, v01);
            *(__nv_bfloat162*)(Y + (size_t)p2*Cout + cg) = __floats2bfloat162_rn(v10, v11);
        }
    }
}

// ---------------- pool + channel attention -----------------------------------
__global__ void pool_kernel(const bf16* __restrict__ cv2b, float* __restrict__ pp) {
    int blk = blockIdx.x;
    int b = blk >> 6, chunk = blk & 63;
    int c = threadIdx.x;
    float s = 0.f;
    int base = b*16384 + chunk*256;
    for (int p = 0; p < 256; p++) s += __bfloat162float(cv2b[(size_t)(base + p)*Cc + c]);
    pp[blk*Cc + c] = s;
}

__global__ void ca_kernel(const float* __restrict__ pp,
                          const float* __restrict__ w1, const float* __restrict__ b1,
                          const float* __restrict__ w2, const float* __restrict__ b2,
                          float* __restrict__ ca) {
    __shared__ float pooled[Bc*Cc];
    __shared__ float t1[Bc*6];
    int tid = threadIdx.x;
    for (int i = tid; i < Bc*Cc; i += 256) {
        int b = i / Cc, c = i % Cc;
        float s = 0.f;
        for (int j = 0; j < 64; j++) s += pp[(b*64 + j)*Cc + c];
        pooled[i] = s * (1.f/16384.f);
    }
    __syncthreads();
    if (tid < Bc*6) {
        int b = tid / 6, j = tid % 6;
        float s = b1[j];
        for (int c = 0; c < Cc; c++) s += pooled[b*Cc + c] * w1[c*6 + j];
        t1[tid] = fmaxf(s, 0.f);
    }
    __syncthreads();
    for (int i = tid; i < Bc*Cc; i += 256) {
        int b = i / Cc, c = i % Cc;
        float s = b2[c];
        #pragma unroll
        for (int j = 0; j < 6; j++) s += t1[b*6 + j] * w2[j*Cc + c];
        ca[i] = 1.f / (1.f + expf(-s));
    }
}

// ---------------- flash window attention via tensor-core MMA ------------------
__global__ __launch_bounds__(256) void attn_mma(
        const bf16* __restrict__ qkvb, const bf16* __restrict__ btb,
        bf16* __restrict__ out) {
    extern __shared__ __align__(16) bf16 smA[];
    bf16* Qs = smA;
    bf16* Ks = smA + 256*QP;
    bf16* Vs = smA + 2*256*QP;
    int win = blockIdx.x, h = blockIdx.y;
    int tid = threadIdx.x;
    int warp = tid >> 5, lane = tid & 31;
    int g = lane >> 2, tg = lane & 3;
    int m0 = warp * 32;

    {
        const uint4* src = (const uint4*)(qkvb + (size_t)(win*Nc + tid)*576 + h*HDc);
        uint4* qd = (uint4*)(Qs + tid*QP);
        uint4* kd = (uint4*)(Ks + tid*QP);
        uint4* vd = (uint4*)(Vs + tid*QP);
        #pragma unroll
        for (int i = 0; i < 4; i++) {
            qd[i] = src[i];
            kd[i] = src[i + 24];
            vd[i] = src[i + 48];
        }
    }
    __syncthreads();

    uint32_t qf[2][2][4];
    #pragma unroll
    for (int mi = 0; mi < 2; mi++)
        #pragma unroll
        for (int ks = 0; ks < 2; ks++) {
            int r = m0 + mi*16 + (lane & 15);
            int kofs = ks*16 + ((lane >> 4) << 3);
            ldsm4(qf[mi][ks], (uint32_t)__cvta_generic_to_shared(Qs + r*QP + kofs));
        }

    const bf16* cb = btb + ((size_t)h << 16);

    int wl = win & 63;
    bool er = (wl >> 3) == 7, ec = (wl & 7) == 7;
    bool edge = er || ec;
    int lq[2][2];
    #pragma unroll
    for (int mi = 0; mi < 2; mi++)
        #pragma unroll
        for (int rh = 0; rh < 2; rh++) {
            int q = m0 + mi*16 + g + rh*8;
            int rc = er ? (((q >> 4) < 8) ? 1 : 2) : 0;
            int cc = ec ? (((q & 15) < 8) ? 1 : 2) : 0;
            lq[mi][rh] = rc*3 + cc;
        }

    float mx[2][2], lsum[2][2];
    float o[2][4][4];
    #pragma unroll
    for (int mi = 0; mi < 2; mi++)
        #pragma unroll
        for (int rh = 0; rh < 2; rh++) { mx[mi][rh] = -1e30f; lsum[mi][rh] = 0.f; }
    #pragma unroll
    for (int mi = 0; mi < 2; mi++)
        #pragma unroll
        for (int nt = 0; nt < 4; nt++)
            #pragma unroll
            for (int e = 0; e < 4; e++) o[mi][nt][e] = 0.f;

    for (int c0 = 0; c0 < Nc; c0 += 32) {
        float s[2][4][4];
        #pragma unroll
        for (int mi = 0; mi < 2; mi++)
            #pragma unroll
            for (int nj = 0; nj < 4; nj++)
                #pragma unroll
                for (int e = 0; e < 4; e++) s[mi][nj][e] = 0.f;

        #pragma unroll
        for (int ks = 0; ks < 2; ks++) {
            uint32_t kf[2][4];
            #pragma unroll
            for (int np = 0; np < 2; np++) {
                int n = c0 + np*16 + (lane & 7) + ((lane >> 4) << 3);
                int kc = ks*16 + ((lane >> 3) & 1)*8;
                ldsm4(kf[np], (uint32_t)__cvta_generic_to_shared(Ks + n*QP + kc));
            }
            #pragma unroll
            for (int mi = 0; mi < 2; mi++) {
                mma_bf16(s[mi][0], qf[mi][ks], &kf[0][0]);
                mma_bf16(s[mi][1], qf[mi][ks], &kf[0][2]);
                mma_bf16(s[mi][2], qf[mi][ks], &kf[1][0]);
                mma_bf16(s[mi][3], qf[mi][ks], &kf[1][2]);
            }
        }

        int lk[4][2];
        if (edge) {
            #pragma unroll
            for (int nj = 0; nj < 4; nj++)
                #pragma unroll
                for (int e = 0; e < 2; e++) {
                    int kcol = c0 + nj*8 + tg*2 + e;
                    int rc = er ? (((kcol >> 4) < 8) ? 1 : 2) : 0;
                    int cc = ec ? (((kcol & 15) < 8) ? 1 : 2) : 0;
                    lk[nj][e] = rc*3 + cc;
                }
        }
        #pragma unroll
        for (int mi = 0; mi < 2; mi++) {
            int row0 = m0 + mi*16 + g;
            #pragma unroll
            for (int nj = 0; nj < 4; nj++) {
                int col = c0 + nj*8 + tg*2;
                float2 b0 = __bfloat1622float2(*(const __nv_bfloat162*)(cb + (size_t)row0*Nc + col));
                float2 b1 = __bfloat1622float2(*(const __nv_bfloat162*)(cb + (size_t)(row0+8)*Nc + col));
                s[mi][nj][0] = s[mi][nj][0]*ATT_SCALE + b0.x;
                s[mi][nj][1] = s[mi][nj][1]*ATT_SCALE + b0.y;
                s[mi][nj][2] = s[mi][nj][2]*ATT_SCALE + b1.x;
                s[mi][nj][3] = s[mi][nj][3]*ATT_SCALE + b1.y;
                if (edge) {
                    s[mi][nj][0] += (lq[mi][0] == lk[nj][0]) ? 0.f : -100.f;
                    s[mi][nj][1] += (lq[mi][0] == lk[nj][1]) ? 0.f : -100.f;
                    s[mi][nj][2] += (lq[mi][1] == lk[nj][0]) ? 0.f : -100.f;
                    s[mi][nj][3] += (lq[mi][1] == lk[nj][1]) ? 0.f : -100.f;
                }
            }
            #pragma unroll
            for (int rh = 0; rh < 2; rh++) {
                int e0 = rh*2;
                float m_ = fmaxf(fmaxf(s[mi][0][e0], s[mi][0][e0+1]),
                                 fmaxf(s[mi][1][e0], s[mi][1][e0+1]));
                m_ = fmaxf(m_, fmaxf(fmaxf(s[mi][2][e0], s[mi][2][e0+1]),
                                     fmaxf(s[mi][3][e0], s[mi][3][e0+1])));
                m_ = fmaxf(m_, __shfl_xor_sync(0xffffffffu, m_, 1));
                m_ = fmaxf(m_, __shfl_xor_sync(0xffffffffu, m_, 2));
                float newm = fmaxf(mx[mi][rh], m_);
                float sc = __expf(mx[mi][rh] - newm);
                mx[mi][rh] = newm;
                float ps = 0.f;
                #pragma unroll
                for (int nj = 0; nj < 4; nj++) {
                    float p0 = __expf(s[mi][nj][e0]   - newm);
                    float p1 = __expf(s[mi][nj][e0+1] - newm);
                    s[mi][nj][e0] = p0; s[mi][nj][e0+1] = p1;
                    ps += p0 + p1;
                }
                ps += __shfl_xor_sync(0xffffffffu, ps, 1);
                ps += __shfl_xor_sync(0xffffffffu, ps, 2);
                lsum[mi][rh] = lsum[mi][rh]*sc + ps;
                #pragma unroll
                for (int nt = 0; nt < 4; nt++) {
                    o[mi][nt][e0]   *= sc;
                    o[mi][nt][e0+1] *= sc;
                }
            }
        }

        #pragma unroll
        for (int ks2 = 0; ks2 < 2; ks2++) {
            uint32_t vf[2][4];
            int krow = c0 + ks2*16 + (lane & 7) + (lane & 8);
            #pragma unroll
            for (int dp = 0; dp < 2; dp++)
                ldsm4t(vf[dp], (uint32_t)__cvta_generic_to_shared(
                    Vs + krow*QP + dp*16 + ((lane >> 4) << 3)));
            #pragma unroll
            for (int mi = 0; mi < 2; mi++) {
                uint32_t af[4];
                af[0] = pkbf2(s[mi][2*ks2][0],   s[mi][2*ks2][1]);
                af[1] = pkbf2(s[mi][2*ks2][2],   s[mi][2*ks2][3]);
                af[2] = pkbf2(s[mi][2*ks2+1][0], s[mi][2*ks2+1][1]);
                af[3] = pkbf2(s[mi][2*ks2+1][2], s[mi][2*ks2+1][3]);
                mma_bf16(o[mi][0], af, &vf[0][0]);
                mma_bf16(o[mi][1], af, &vf[0][2]);
                mma_bf16(o[mi][2], af, &vf[1][0]);
                mma_bf16(o[mi][3], af, &vf[1][2]);
            }
        }
    }

    #pragma unroll
    for (int mi = 0; mi < 2; mi++) {
        #pragma unroll
        for (int rh = 0; rh < 2; rh++) {
            float inv = 1.f / lsum[mi][rh];
            int row = win*Nc + m0 + mi*16 + g + rh*8;
            bf16* orow = out + (size_t)row*Cc + h*HDc;
            #pragma unroll
            for (int nt = 0; nt < 4; nt++) {
                *(__nv_bfloat162*)(orow + nt*8 + tg*2) =
                    __floats2bfloat162_rn(o[mi][nt][rh*2]*inv, o[mi][nt][rh*2+1]*inv);
            }
        }
    }
}

// ---------------- launch -----------------------------------------------------
extern "C" void kernel_launch(void* const* d_in, const int* in_sizes, int n_in,
                              void* d_out, int out_size) {
    const float* x     = (const float*)d_in[0];
    const float* qkv_w = (const float*)d_in[1];
    const float* qkv_b = (const float*)d_in[2];
    const float* proj_w= (const float*)d_in[3];
    const float* proj_b= (const float*)d_in[4];
    const float* rpb   = (const float*)d_in[5];
    const float* n1w   = (const float*)d_in[6];
    const float* n1b   = (const float*)d_in[7];
    const float* n2w   = (const float*)d_in[8];
    const float* n2b   = (const float*)d_in[9];
    const float* c1w   = (const float*)d_in[10];
    const float* c1b   = (const float*)d_in[11];
    const float* c2w   = (const float*)d_in[12];
    const float* c2b   = (const float*)d_in[13];
    const float* ca1w  = (const float*)d_in[14];
    const float* ca1b  = (const float*)d_in[15];
    const float* ca2w  = (const float*)d_in[16];
    const float* ca2b  = (const float*)d_in[17];
    const float* fc1w  = (const float*)d_in[18];
    const float* fc1b  = (const float*)d_in[19];
    const float* fc2w  = (const float*)d_in[20];
    const float* fc2b  = (const float*)d_in[21];
    const int*   rpi   = (const int*)d_in[22];
    float* out = (float*)d_out;

    bf16 *xnb, *qkvb, *atb, *cv1b, *cv2b, *ynb, *hb, *btb;
    bf16 *wqkv, *wproj, *wfc1, *wfc2, *wc1, *wc2;
    float *y, *pp, *cab;
    cudaGetSymbolAddress((void**)&xnb,  g_xnb);
    cudaGetSymbolAddress((void**)&qkvb, g_qkvb);
    cudaGetSymbolAddress((void**)&atb,  g_atb);
    cudaGetSymbolAddress((void**)&cv1b, g_cv1b);
    cudaGetSymbolAddress((void**)&cv2b, g_cv2b);
    cudaGetSymbolAddress((void**)&y,    g_y);
    cudaGetSymbolAddress((void**)&ynb,  g_ynb);
    cudaGetSymbolAddress((void**)&hb,   g_hb);
    cudaGetSymbolAddress((void**)&pp,   g_pp);
    cudaGetSymbolAddress((void**)&cab,  g_ca);
    cudaGetSymbolAddress((void**)&btb,  g_btb);
    cudaGetSymbolAddress((void**)&wqkv, g_wqkv);
    cudaGetSymbolAddress((void**)&wproj,g_wproj);
    cudaGetSymbolAddress((void**)&wfc1, g_wfc1);
    cudaGetSymbolAddress((void**)&wfc2, g_wfc2);
    cudaGetSymbolAddress((void**)&wc1,  g_wc1);
    cudaGetSymbolAddress((void**)&wc2,  g_wc2);

    static bool attr_set = false;
    if (!attr_set) {
        cudaFuncSetAttribute(attn_mma, cudaFuncAttributeMaxDynamicSharedMemorySize,
                             3*256*QP*sizeof(bf16));
        attr_set = true;
    }

    f2b_all<<<(STOT + 255)/256, 256>>>(qkv_w, proj_w, fc1w, fc2w, c1w, c2w,
                                       wqkv, wproj, wfc1, wfc2, wc1, wc2);
    btb_kernel<<<NHc*Nc*Nc/256, 256>>>(rpb, rpi, btb);

    ln_kernel<<<NPIX/8, 256>>>(x, n1w, n1b, xnb);
    // conv branch
    mma_conv<1, Cc, 64><<<dim3(Bc*Hc, 1), 256>>>(xnb, wc1, c1b, cv1b);
    mma_conv<0, 64, Cc><<<dim3(Bc*Hc, 3), 256>>>(cv1b, wc2, c2b, cv2b);
    pool_kernel<<<Bc*64, Cc>>>(cv2b, pp);
    ca_kernel<<<1, 256>>>(pp, ca1w, ca1b, ca2w, ca2b, cab);
    // attention branch
    mma_gemm<0, 1, Cc, 3*Cc><<<dim3(NPIX/128, 9), 256>>>(xnb, wqkv, qkv_b, qkvb,
                                                         nullptr, nullptr, nullptr, nullptr);
    attn_mma<<<dim3(256, NHc), 256, 3*256*QP*sizeof(bf16)>>>(qkvb, btb, atb);
    mma_gemm<3, 0, Cc, Cc><<<dim3(NPIX/128, 3), 256>>>(atb, wproj, proj_b, y,
                                                       nullptr, x, cv2b, cab);
    // MLP
    ln_kernel<<<NPIX/8, 256>>>(y, n2w, n2b, ynb);
    mma_gemm<1, 0, Cc, 4*Cc><<<dim3(NPIX/128, 12), 256>>>(ynb, wfc1, fc1b, hb,
                                                          nullptr, nullptr, nullptr, nullptr);
    mma_gemm<2, 0, 4*Cc, Cc><<<dim3(NPIX/128, 3), 256>>>(hb, wfc2, fc2b, out,
                                                         y, nullptr, nullptr, nullptr);
}